// round 1
// baseline (speedup 1.0000x reference)
#include <cuda_runtime.h>
#include <math.h>

#define Bsz   8192
#define Hdim  1024
#define H2    512
#define G3    3072
#define T_PAST 60
#define T_FUT  30

// ---- scratch (static device globals; no allocation allowed) ----
__device__ float g_ec[Bsz * H2];            // relu(context @ wc.T + bc)     16.8 MB
__device__ float g_gi1[Bsz * G3];           // ec @ gru1_wi.T + gru1_bi     100.7 MB
__device__ float g_gi2[Bsz * G3];           // ec @ gru2_wi.T + gru2_bi     100.7 MB
__device__ float g_h[2][2][Bsz * Hdim];     // [gru][pingpong] hidden state 134 MB

// ---------------------------------------------------------------------------
// init: h0 = context for both GRUs
// ---------------------------------------------------------------------------
__global__ void init_h_kernel(const float* __restrict__ ctx) {
    int i = blockIdx.x * blockDim.x + threadIdx.x;
    const int n = Bsz * Hdim;
    const int stride = gridDim.x * blockDim.x;
    for (; i < n; i += stride) {
        float v = ctx[i];
        g_h[0][0][i] = v;
        g_h[1][0][i] = v;
    }
}

// ---------------------------------------------------------------------------
// Generic C[M,N] = act(A[M,K] @ W[N,K]^T + bias[N]); M,N mult of 64, K mult of 16
// 64x64 tile, 256 threads, 4x4 micro-tile per thread.
// ---------------------------------------------------------------------------
__global__ void gemm_bt_kernel(const float* __restrict__ A,
                               const float* __restrict__ W,
                               const float* __restrict__ bias,
                               float* __restrict__ C,
                               int N, int K, int relu) {
    __shared__ float As[16][68];
    __shared__ float Bs[16][68];
    const int t   = threadIdx.x;
    const int tx  = t & 15, ty = t >> 4;
    const int m0  = blockIdx.y << 6, n0 = blockIdx.x << 6;
    const int lrow = t >> 2;            // 0..63
    const int lk   = (t & 3) << 2;      // 0,4,8,12

    float acc[4][4] = {};
    const float* Ap = A + (size_t)(m0 + lrow) * K + lk;
    const float* Wp = W + (size_t)(n0 + lrow) * K + lk;

    for (int k0 = 0; k0 < K; k0 += 16) {
        float4 a = *(const float4*)(Ap + k0);
        float4 b = *(const float4*)(Wp + k0);
        __syncthreads();
        As[lk + 0][lrow] = a.x; As[lk + 1][lrow] = a.y;
        As[lk + 2][lrow] = a.z; As[lk + 3][lrow] = a.w;
        Bs[lk + 0][lrow] = b.x; Bs[lk + 1][lrow] = b.y;
        Bs[lk + 2][lrow] = b.z; Bs[lk + 3][lrow] = b.w;
        __syncthreads();
#pragma unroll
        for (int k = 0; k < 16; k++) {
            float4 av = *(const float4*)&As[k][ty << 2];
            float4 bv = *(const float4*)&Bs[k][tx << 2];
            float aa[4] = {av.x, av.y, av.z, av.w};
            float bb[4] = {bv.x, bv.y, bv.z, bv.w};
#pragma unroll
            for (int i = 0; i < 4; i++)
#pragma unroll
                for (int j = 0; j < 4; j++)
                    acc[i][j] += aa[i] * bb[j];
        }
    }

#pragma unroll
    for (int i = 0; i < 4; i++) {
        int m = m0 + (ty << 2) + i;
#pragma unroll
        for (int j = 0; j < 4; j++) {
            int n = n0 + (tx << 2) + j;
            float v = acc[i][j] + bias[n];
            if (relu) v = fmaxf(v, 0.0f);
            C[(size_t)m * N + n] = v;
        }
    }
}

// ---------------------------------------------------------------------------
// Fused GRU step: gh = h @ wh^T (+bh), gates, h_new -> pingpong buffer.
// One CTA: 64(batch) x 64(hidden-col) tile of h_new; 3 gate GEMM tiles, K=1024.
// ---------------------------------------------------------------------------
__global__ void gru_step_kernel(const float* __restrict__ wh,
                                const float* __restrict__ bh,
                                int gru, int cur) {
    __shared__ float As [16][68];
    __shared__ float Bs0[16][68];
    __shared__ float Bs1[16][68];
    __shared__ float Bs2[16][68];

    const float* gi   = gru ? g_gi2 : g_gi1;
    const float* hin  = g_h[gru][cur];
    float*       hout = g_h[gru][cur ^ 1];

    const int t    = threadIdx.x;
    const int tx   = t & 15, ty = t >> 4;
    const int m0   = blockIdx.y << 6, n0 = blockIdx.x << 6;
    const int lrow = t >> 2;
    const int lk   = (t & 3) << 2;

    float acc[3][4][4] = {};

    const float* Ap = hin + (size_t)(m0 + lrow) * Hdim + lk;
    const float* W0 = wh  + (size_t)(0 * Hdim + n0 + lrow) * Hdim + lk;
    const float* W1 = wh  + (size_t)(1 * Hdim + n0 + lrow) * Hdim + lk;
    const float* W2 = wh  + (size_t)(2 * Hdim + n0 + lrow) * Hdim + lk;

    for (int k0 = 0; k0 < Hdim; k0 += 16) {
        float4 a  = *(const float4*)(Ap + k0);
        float4 b0 = *(const float4*)(W0 + k0);
        float4 b1 = *(const float4*)(W1 + k0);
        float4 b2 = *(const float4*)(W2 + k0);
        __syncthreads();
        As [lk + 0][lrow] = a.x;  As [lk + 1][lrow] = a.y;
        As [lk + 2][lrow] = a.z;  As [lk + 3][lrow] = a.w;
        Bs0[lk + 0][lrow] = b0.x; Bs0[lk + 1][lrow] = b0.y;
        Bs0[lk + 2][lrow] = b0.z; Bs0[lk + 3][lrow] = b0.w;
        Bs1[lk + 0][lrow] = b1.x; Bs1[lk + 1][lrow] = b1.y;
        Bs1[lk + 2][lrow] = b1.z; Bs1[lk + 3][lrow] = b1.w;
        Bs2[lk + 0][lrow] = b2.x; Bs2[lk + 1][lrow] = b2.y;
        Bs2[lk + 2][lrow] = b2.z; Bs2[lk + 3][lrow] = b2.w;
        __syncthreads();
#pragma unroll
        for (int k = 0; k < 16; k++) {
            float4 av = *(const float4*)&As [k][ty << 2];
            float4 v0 = *(const float4*)&Bs0[k][tx << 2];
            float4 v1 = *(const float4*)&Bs1[k][tx << 2];
            float4 v2 = *(const float4*)&Bs2[k][tx << 2];
            float aa[4] = {av.x, av.y, av.z, av.w};
            float r0[4] = {v0.x, v0.y, v0.z, v0.w};
            float r1[4] = {v1.x, v1.y, v1.z, v1.w};
            float r2[4] = {v2.x, v2.y, v2.z, v2.w};
#pragma unroll
            for (int i = 0; i < 4; i++) {
#pragma unroll
                for (int j = 0; j < 4; j++) {
                    acc[0][i][j] += aa[i] * r0[j];
                    acc[1][i][j] += aa[i] * r1[j];
                    acc[2][i][j] += aa[i] * r2[j];
                }
            }
        }
    }

    // epilogue: GRU cell
#pragma unroll
    for (int i = 0; i < 4; i++) {
        int b = m0 + (ty << 2) + i;
        const float* gib = gi + (size_t)b * G3;
#pragma unroll
        for (int j = 0; j < 4; j++) {
            int col = n0 + (tx << 2) + j;
            float hr = acc[0][i][j] + bh[col];
            float hz = acc[1][i][j] + bh[Hdim + col];
            float hn = acc[2][i][j] + bh[2 * Hdim + col];
            float ir  = gib[col];
            float iz  = gib[Hdim + col];
            float inn = gib[2 * Hdim + col];
            float r = 1.0f / (1.0f + expf(-(ir + hr)));
            float z = 1.0f / (1.0f + expf(-(iz + hz)));
            float n = tanhf(inn + r * hn);
            float ho = hin[(size_t)b * Hdim + col];
            hout[(size_t)b * Hdim + col] = (1.0f - z) * n + z * ho;
        }
    }
}

// ---------------------------------------------------------------------------
// Per-step projection: out[b, t, 0..3] = (relu?)(h[b,:]) . w[i,:] + bias[i]
// 4 warps/block, warp-per-row; weights staged in smem.
// ---------------------------------------------------------------------------
__global__ void proj4_kernel(int gru, int buf,
                             const float* __restrict__ w,      // [4, H]
                             const float* __restrict__ bias,   // [4]
                             float* __restrict__ out,
                             int t, int T, int relu) {
    __shared__ float ws[4 * Hdim];
    const int tid = threadIdx.x;
    for (int i = tid * 4; i < 4 * Hdim; i += blockDim.x * 4)
        *(float4*)&ws[i] = *(const float4*)(w + i);
    __syncthreads();

    const float* hbuf = g_h[gru][buf];
    const int warp = tid >> 5, lane = tid & 31;
    const int b = blockIdx.x * 4 + warp;
    const float* hrow = hbuf + (size_t)b * Hdim;

    float a0 = 0.f, a1 = 0.f, a2 = 0.f, a3 = 0.f;
    for (int j = lane; j < Hdim; j += 32) {
        float hv = hrow[j];
        if (relu) hv = fmaxf(hv, 0.0f);
        a0 += hv * ws[j];
        a1 += hv * ws[Hdim + j];
        a2 += hv * ws[2 * Hdim + j];
        a3 += hv * ws[3 * Hdim + j];
    }
#pragma unroll
    for (int off = 16; off; off >>= 1) {
        a0 += __shfl_down_sync(0xffffffffu, a0, off);
        a1 += __shfl_down_sync(0xffffffffu, a1, off);
        a2 += __shfl_down_sync(0xffffffffu, a2, off);
        a3 += __shfl_down_sync(0xffffffffu, a3, off);
    }
    if (lane == 0) {
        float* o = out + (size_t)b * T * 4 + (size_t)t * 4;
        o[0] = a0 + bias[0];
        o[1] = a1 + bias[1];
        o[2] = a2 + bias[2];
        o[3] = a3 + bias[3];
    }
}

// ---------------------------------------------------------------------------
extern "C" void kernel_launch(void* const* d_in, const int* in_sizes, int n_in,
                              void* d_out, int out_size) {
    const float* context = (const float*)d_in[0];
    const float* wc      = (const float*)d_in[1];
    const float* bc      = (const float*)d_in[2];
    const float* g1wi    = (const float*)d_in[3];
    const float* g1wh    = (const float*)d_in[4];
    const float* g1bi    = (const float*)d_in[5];
    const float* g1bh    = (const float*)d_in[6];
    const float* g2wi    = (const float*)d_in[7];
    const float* g2wh    = (const float*)d_in[8];
    const float* g2bi    = (const float*)d_in[9];
    const float* g2bh    = (const float*)d_in[10];
    const float* fiw     = (const float*)d_in[11];
    const float* fib     = (const float*)d_in[12];
    const float* fow     = (const float*)d_in[13];
    const float* fob     = (const float*)d_in[14];
    // d_in[15]/d_in[16]: future_length=30 / past_length=60 (compile-time fixed)

    float* dec = (float*)d_out;                               // [B, 60, 4]
    float* fut = (float*)d_out + (size_t)Bsz * T_PAST * 4;    // [B, 30, 4]

    float *ec_p, *gi1_p, *gi2_p;
    cudaGetSymbolAddress((void**)&ec_p,  g_ec);
    cudaGetSymbolAddress((void**)&gi1_p, g_gi1);
    cudaGetSymbolAddress((void**)&gi2_p, g_gi2);

    // ec = relu(context @ wc.T + bc)  [B, 512]
    gemm_bt_kernel<<<dim3(H2 / 64, Bsz / 64), 256>>>(context, wc, bc, ec_p, H2, Hdim, 1);
    // gi = ec @ wi.T + bi  [B, 3072] (loop-invariant input gates)
    gemm_bt_kernel<<<dim3(G3 / 64, Bsz / 64), 256>>>(ec_p, g1wi, g1bi, gi1_p, G3, H2, 0);
    gemm_bt_kernel<<<dim3(G3 / 64, Bsz / 64), 256>>>(ec_p, g2wi, g2bi, gi2_p, G3, H2, 0);
    // h0 = context
    init_h_kernel<<<1024, 256>>>(context);

    const dim3 step_grid(Hdim / 64, Bsz / 64);
    for (int t = 0; t < T_PAST; t++) {
        int cur = t & 1;
        gru_step_kernel<<<step_grid, 256>>>(g1wh, g1bh, 0, cur);
        proj4_kernel<<<Bsz / 4, 128>>>(0, cur ^ 1, fiw, fib, dec, t, T_PAST, 0);
        if (t < T_FUT) {
            gru_step_kernel<<<step_grid, 256>>>(g2wh, g2bh, 1, cur);
            proj4_kernel<<<Bsz / 4, 128>>>(1, cur ^ 1, fow, fob, fut, t, T_FUT, 1);
        }
    }
}

// round 5
// speedup vs baseline: 2.0092x; 2.0092x over previous
#include <cuda_runtime.h>
#include <cuda_bf16.h>
#include <cstdint>
#include <math.h>

#define Bsz   8192
#define Hdim  1024
#define H2    512
#define G3    3072
#define T_PAST 60
#define T_FUT  30

// ---------------- scratch (static device globals) ----------------
__device__ float g_ec[Bsz * H2];
__device__ float g_gi1[Bsz * G3];
__device__ float g_gi2[Bsz * G3];
__device__ float g_h[2][2][Bsz * Hdim];                  // fp32 hidden, [gru][pp]
__device__ __nv_bfloat16 g_ahi[2][2][Bsz * Hdim];        // h split hi
__device__ __nv_bfloat16 g_alo[2][2][Bsz * Hdim];        // h split lo
__device__ __nv_bfloat16 g_whi[2][G3 * Hdim];            // wh split hi
__device__ __nv_bfloat16 g_wlo[2][G3 * Hdim];            // wh split lo

// ---------------- PTX helpers (all sm_80-level, compute_103-safe) ----------------
__device__ __forceinline__ uint32_t smem_u32(const void* p) {
    uint32_t a;
    asm("{ .reg .u64 t; cvta.to.shared.u64 t, %1; cvt.u32.u64 %0, t; }" : "=r"(a) : "l"(p));
    return a;
}
__device__ __forceinline__ void cp16(uint32_t s, const void* g) {
    asm volatile("cp.async.cg.shared.global [%0], [%1], 16;" :: "r"(s), "l"(g));
}
__device__ __forceinline__ void cp_commit() {
    asm volatile("cp.async.commit_group;" ::: "memory");
}
template <int N> __device__ __forceinline__ void cp_wait() {
    asm volatile("cp.async.wait_group %0;" :: "n"(N) : "memory");
}
__device__ __forceinline__ void ldsm_x4(uint32_t* r, uint32_t a) {
    asm volatile("ldmatrix.sync.aligned.m8n8.x4.shared.b16 {%0,%1,%2,%3}, [%4];"
                 : "=r"(r[0]), "=r"(r[1]), "=r"(r[2]), "=r"(r[3]) : "r"(a));
}
__device__ __forceinline__ void mma_bf16(float* c, const uint32_t* a, const uint32_t* b) {
    asm volatile(
        "mma.sync.aligned.m16n8k16.row.col.f32.bf16.bf16.f32 "
        "{%0,%1,%2,%3}, {%4,%5,%6,%7}, {%8,%9}, {%0,%1,%2,%3};"
        : "+f"(c[0]), "+f"(c[1]), "+f"(c[2]), "+f"(c[3])
        : "r"(a[0]), "r"(a[1]), "r"(a[2]), "r"(a[3]), "r"(b[0]), "r"(b[1]));
}

// ---------------- small kernels ----------------
__global__ void split_w_kernel(const float* __restrict__ src,
                               __nv_bfloat16* __restrict__ hi,
                               __nv_bfloat16* __restrict__ lo, int n) {
    int i = blockIdx.x * blockDim.x + threadIdx.x;
    int stride = gridDim.x * blockDim.x;
    for (; i < n; i += stride) {
        float f = src[i];
        __nv_bfloat16 h = __float2bfloat16(f);
        hi[i] = h;
        lo[i] = __float2bfloat16(f - __bfloat162float(h));
    }
}

__global__ void init_h_kernel(const float* __restrict__ ctx) {
    int i = blockIdx.x * blockDim.x + threadIdx.x;
    const int n = Bsz * Hdim;
    const int stride = gridDim.x * blockDim.x;
    for (; i < n; i += stride) {
        float v = ctx[i];
        __nv_bfloat16 h = __float2bfloat16(v);
        __nv_bfloat16 l = __float2bfloat16(v - __bfloat162float(h));
        g_h[0][0][i] = v;   g_h[1][0][i] = v;
        g_ahi[0][0][i] = h; g_ahi[1][0][i] = h;
        g_alo[0][0][i] = l; g_alo[1][0][i] = l;
    }
}

// fp32 SIMT GEMM for prologue: C = act(A @ W^T + bias)
__global__ void gemm_bt_kernel(const float* __restrict__ A,
                               const float* __restrict__ W,
                               const float* __restrict__ bias,
                               float* __restrict__ C,
                               int N, int K, int relu) {
    __shared__ float As[16][68];
    __shared__ float Bs[16][68];
    const int t   = threadIdx.x;
    const int tx  = t & 15, ty = t >> 4;
    const int m0  = blockIdx.y << 6, n0 = blockIdx.x << 6;
    const int lrow = t >> 2;
    const int lk   = (t & 3) << 2;

    float acc[4][4] = {};
    const float* Ap = A + (size_t)(m0 + lrow) * K + lk;
    const float* Wp = W + (size_t)(n0 + lrow) * K + lk;

    for (int k0 = 0; k0 < K; k0 += 16) {
        float4 a = *(const float4*)(Ap + k0);
        float4 b = *(const float4*)(Wp + k0);
        __syncthreads();
        As[lk + 0][lrow] = a.x; As[lk + 1][lrow] = a.y;
        As[lk + 2][lrow] = a.z; As[lk + 3][lrow] = a.w;
        Bs[lk + 0][lrow] = b.x; Bs[lk + 1][lrow] = b.y;
        Bs[lk + 2][lrow] = b.z; Bs[lk + 3][lrow] = b.w;
        __syncthreads();
#pragma unroll
        for (int k = 0; k < 16; k++) {
            float4 av = *(const float4*)&As[k][ty << 2];
            float4 bv = *(const float4*)&Bs[k][tx << 2];
            float aa[4] = {av.x, av.y, av.z, av.w};
            float bb[4] = {bv.x, bv.y, bv.z, bv.w};
#pragma unroll
            for (int i = 0; i < 4; i++)
#pragma unroll
                for (int j = 0; j < 4; j++)
                    acc[i][j] += aa[i] * bb[j];
        }
    }
#pragma unroll
    for (int i = 0; i < 4; i++) {
        int m = m0 + (ty << 2) + i;
#pragma unroll
        for (int j = 0; j < 4; j++) {
            int n = n0 + (tx << 2) + j;
            float v = acc[i][j] + bias[n];
            if (relu) v = fmaxf(v, 0.0f);
            C[(size_t)m * N + n] = v;
        }
    }
}

// ---------------- HMMA fused GRU step ----------------
// Stage layout (bytes, rows padded to 48B for conflict-free ldmatrix):
static constexpr int OFF_ALO   = 128 * 48;               // 6144
static constexpr int OFF_WHI   = 2 * 128 * 48;           // 12288
static constexpr int WLODELTA  = 192 * 48;               // 9216
static constexpr int STAGE     = OFF_WHI + 2 * 192 * 48; // 30720
static constexpr int NS        = 4;
static constexpr int DYN_SMEM  = NS * STAGE + 256;       // ~123 KB

__global__ void __launch_bounds__(256, 1)
gru_step_mma(const float* __restrict__ gi, const float* __restrict__ bh,
             const __nv_bfloat16* __restrict__ whi, const __nv_bfloat16* __restrict__ wlo,
             const __nv_bfloat16* __restrict__ ahi, const __nv_bfloat16* __restrict__ alo,
             const float* __restrict__ hin, float* __restrict__ hout,
             __nv_bfloat16* __restrict__ ohi, __nv_bfloat16* __restrict__ olo) {
    extern __shared__ char dsmem[];
    __shared__ float s_bh[192];

    const int t   = threadIdx.x;
    const int wid = t >> 5, L = t & 31;
    const int n0  = blockIdx.x * 64;     // per-gate column tile
    const int m0  = blockIdx.y * 128;    // batch tile
    const int mwarp = wid >> 1, nwarp = wid & 1;

    uint32_t dynb = (smem_u32(dsmem) + 127u) & ~127u;

    if (t < 192) s_bh[t] = bh[(t >> 6) * 1024 + n0 + (t & 63)];

    // ---- per-thread cp.async chunk assignments ----
    const int ar = t >> 1, ah = t & 1;
    const __nv_bfloat16* srcAhi = ahi + (size_t)(m0 + ar) * Hdim + 8 * ah;
    const __nv_bfloat16* srcAlo = alo + (size_t)(m0 + ar) * Hdim + 8 * ah;
    const uint32_t dA = (uint32_t)(ar * 48 + ah * 16);
    const int w1row = t >> 1, w1h = t & 1;
    const int g1 = w1row >> 6, n1 = w1row & 63;
    const __nv_bfloat16* srcW1h = whi + (size_t)(g1 * 1024 + n0 + n1) * Hdim + 8 * w1h;
    const __nv_bfloat16* srcW1l = wlo + (size_t)(g1 * 1024 + n0 + n1) * Hdim + 8 * w1h;
    const uint32_t dW1 = (uint32_t)(OFF_WHI + w1row * 48 + w1h * 16);
    const int w2row = 128 + (t >> 1), w2h = t & 1;
    const int n2 = w2row & 63;
    const __nv_bfloat16* srcW2h = whi + (size_t)(2 * 1024 + n0 + n2) * Hdim + 8 * w2h;
    const __nv_bfloat16* srcW2l = wlo + (size_t)(2 * 1024 + n0 + n2) * Hdim + 8 * w2h;
    const uint32_t dW2 = (uint32_t)(OFF_WHI + w2row * 48 + w2h * 16);

    auto load_stage = [&](uint32_t base, int ke) {
        cp16(base + dA, srcAhi + ke);
        cp16(base + dA + OFF_ALO, srcAlo + ke);
        cp16(base + dW1, srcW1h + ke);
        cp16(base + dW1 + WLODELTA, srcW1l + ke);
        if (t < 128) {
            cp16(base + dW2, srcW2h + ke);
            cp16(base + dW2 + WLODELTA, srcW2l + ke);
        }
    };

    // ---- ldmatrix lane offsets (within stage) ----
    uint32_t aoff[2];
    {
        int r = L & 15, k8 = L >> 4;
        aoff[0] = (uint32_t)((mwarp * 32 + r) * 48 + k8 * 16);
        aoff[1] = aoff[0] + 16 * 48;
    }
    uint32_t boff[3][2];
    {
        int nlane = (L & 7) + ((L & 16) ? 8 : 0);
        int k8 = (L >> 3) & 1;
#pragma unroll
        for (int g = 0; g < 3; g++)
#pragma unroll
            for (int u = 0; u < 2; u++)
                boff[g][u] = (uint32_t)(OFF_WHI +
                    (g * 64 + nwarp * 32 + u * 16 + nlane) * 48 + k8 * 16);
    }

    // ---- pipeline prologue ----
#pragma unroll
    for (int s = 0; s < NS - 1; s++) {
        load_stage(dynb + s * STAGE, s * 16);
        cp_commit();
    }

    float acc[3][2][4][4];
#pragma unroll
    for (int g = 0; g < 3; g++)
#pragma unroll
        for (int mt = 0; mt < 2; mt++)
#pragma unroll
            for (int nt = 0; nt < 4; nt++)
#pragma unroll
                for (int e = 0; e < 4; e++) acc[g][mt][nt][e] = 0.0f;

    // ---- main K loop (64 x k16) ----
#pragma unroll 1
    for (int ki = 0; ki < 64; ki++) {
        cp_wait<NS - 2>();
        __syncthreads();
        const uint32_t sb = dynb + (uint32_t)(ki & 3) * STAGE;

        uint32_t AH[2][4], AL[2][4];
        ldsm_x4(AH[0], sb + aoff[0]);
        ldsm_x4(AH[1], sb + aoff[1]);
        ldsm_x4(AL[0], sb + aoff[0] + OFF_ALO);
        ldsm_x4(AL[1], sb + aoff[1] + OFF_ALO);
#pragma unroll
        for (int g = 0; g < 3; g++) {
            uint32_t BH[2][4], BL[2][4];
            ldsm_x4(BH[0], sb + boff[g][0]);      // non-trans: W stored [n][k]
            ldsm_x4(BH[1], sb + boff[g][1]);
            ldsm_x4(BL[0], sb + boff[g][0] + WLODELTA);
            ldsm_x4(BL[1], sb + boff[g][1] + WLODELTA);
#pragma unroll
            for (int mt = 0; mt < 2; mt++)
#pragma unroll
                for (int nt = 0; nt < 4; nt++) {
                    const uint32_t* bhp = &BH[nt >> 1][(nt & 1) * 2];
                    const uint32_t* blp = &BL[nt >> 1][(nt & 1) * 2];
                    mma_bf16(acc[g][mt][nt], AH[mt], bhp);
                    mma_bf16(acc[g][mt][nt], AH[mt], blp);
                    mma_bf16(acc[g][mt][nt], AL[mt], bhp);
                }
        }

        const int kn = ki + NS - 1;
        if (kn < 64) load_stage(dynb + (uint32_t)(kn & 3) * STAGE, kn * 16);
        cp_commit();
    }

    // ---- fused GRU epilogue (C-fragments in registers) ----
    const int rq = L >> 2, cq = L & 3;
#pragma unroll
    for (int mt = 0; mt < 2; mt++) {
#pragma unroll
        for (int rs = 0; rs < 2; rs++) {
            const int row = m0 + mwarp * 32 + mt * 16 + rs * 8 + rq;
            const float* gib  = gi  + (size_t)row * G3;
            const float* hinr = hin + (size_t)row * Hdim;
            float*       hor  = hout + (size_t)row * Hdim;
            __nv_bfloat16* hhr = ohi + (size_t)row * Hdim;
            __nv_bfloat16* hlr = olo + (size_t)row * Hdim;
#pragma unroll
            for (int nt = 0; nt < 4; nt++) {
                const int c   = nwarp * 32 + nt * 8 + 2 * cq;   // 0..63
                const int col = n0 + c;
                float2 ir  = *(const float2*)(gib + col);
                float2 iz  = *(const float2*)(gib + 1024 + col);
                float2 inn = *(const float2*)(gib + 2048 + col);
                float2 hv  = *(const float2*)(hinr + col);
                float ira[2] = {ir.x, ir.y};
                float iza[2] = {iz.x, iz.y};
                float ina[2] = {inn.x, inn.y};
                float hva[2] = {hv.x, hv.y};
                float o[2];
#pragma unroll
                for (int e = 0; e < 2; e++) {
                    float hr = acc[0][mt][nt][rs * 2 + e] + s_bh[c + e];
                    float hz = acc[1][mt][nt][rs * 2 + e] + s_bh[64 + c + e];
                    float hn = acc[2][mt][nt][rs * 2 + e] + s_bh[128 + c + e];
                    float r = 1.0f / (1.0f + __expf(-(ira[e] + hr)));
                    float z = 1.0f / (1.0f + __expf(-(iza[e] + hz)));
                    float ex = __expf(2.0f * (ina[e] + r * hn));
                    float nn = 1.0f - 2.0f / (ex + 1.0f);
                    o[e] = (1.0f - z) * nn + z * hva[e];
                }
                *(float2*)(hor + col) = make_float2(o[0], o[1]);
                __nv_bfloat16 h0 = __float2bfloat16(o[0]);
                __nv_bfloat16 h1 = __float2bfloat16(o[1]);
                *(__nv_bfloat162*)(hhr + col) = __nv_bfloat162(h0, h1);
                *(__nv_bfloat162*)(hlr + col) = __nv_bfloat162(
                    __float2bfloat16(o[0] - __bfloat162float(h0)),
                    __float2bfloat16(o[1] - __bfloat162float(h1)));
            }
        }
    }
}

// ---------------- per-step 4-col projection ----------------
__global__ void proj4_kernel(const float* __restrict__ hbuf,
                             const float* __restrict__ w,
                             const float* __restrict__ bias,
                             float* __restrict__ out,
                             int tstep, int T, int relu) {
    __shared__ float ws[4 * Hdim];
    const int tid = threadIdx.x;
    for (int i = tid * 4; i < 4 * Hdim; i += blockDim.x * 4)
        *(float4*)&ws[i] = *(const float4*)(w + i);
    __syncthreads();

    const int warp = tid >> 5, lane = tid & 31;
    const int b = blockIdx.x * 4 + warp;
    const float* hrow = hbuf + (size_t)b * Hdim;

    float a0 = 0.f, a1 = 0.f, a2 = 0.f, a3 = 0.f;
    for (int j = lane; j < Hdim; j += 32) {
        float hv = hrow[j];
        if (relu) hv = fmaxf(hv, 0.0f);
        a0 += hv * ws[j];
        a1 += hv * ws[Hdim + j];
        a2 += hv * ws[2 * Hdim + j];
        a3 += hv * ws[3 * Hdim + j];
    }
#pragma unroll
    for (int off = 16; off; off >>= 1) {
        a0 += __shfl_down_sync(0xffffffffu, a0, off);
        a1 += __shfl_down_sync(0xffffffffu, a1, off);
        a2 += __shfl_down_sync(0xffffffffu, a2, off);
        a3 += __shfl_down_sync(0xffffffffu, a3, off);
    }
    if (lane == 0) {
        float* o = out + (size_t)b * T * 4 + (size_t)tstep * 4;
        o[0] = a0 + bias[0];
        o[1] = a1 + bias[1];
        o[2] = a2 + bias[2];
        o[3] = a3 + bias[3];
    }
}

// ---------------------------------------------------------------------------
extern "C" void kernel_launch(void* const* d_in, const int* in_sizes, int n_in,
                              void* d_out, int out_size) {
    const float* context = (const float*)d_in[0];
    const float* wc      = (const float*)d_in[1];
    const float* bc      = (const float*)d_in[2];
    const float* g1wi    = (const float*)d_in[3];
    const float* g1wh    = (const float*)d_in[4];
    const float* g1bi    = (const float*)d_in[5];
    const float* g1bh    = (const float*)d_in[6];
    const float* g2wi    = (const float*)d_in[7];
    const float* g2wh    = (const float*)d_in[8];
    const float* g2bi    = (const float*)d_in[9];
    const float* g2bh    = (const float*)d_in[10];
    const float* fiw     = (const float*)d_in[11];
    const float* fib     = (const float*)d_in[12];
    const float* fow     = (const float*)d_in[13];
    const float* fob     = (const float*)d_in[14];

    float* dec = (float*)d_out;
    float* fut = (float*)d_out + (size_t)Bsz * T_PAST * 4;

    float *ec_p, *gi1_p, *gi2_p, *h_p;
    __nv_bfloat16 *ahi_p, *alo_p, *whi_p, *wlo_p;
    cudaGetSymbolAddress((void**)&ec_p,  g_ec);
    cudaGetSymbolAddress((void**)&gi1_p, g_gi1);
    cudaGetSymbolAddress((void**)&gi2_p, g_gi2);
    cudaGetSymbolAddress((void**)&h_p,   g_h);
    cudaGetSymbolAddress((void**)&ahi_p, g_ahi);
    cudaGetSymbolAddress((void**)&alo_p, g_alo);
    cudaGetSymbolAddress((void**)&whi_p, g_whi);
    cudaGetSymbolAddress((void**)&wlo_p, g_wlo);

    const size_t HN = (size_t)Bsz * Hdim;
    const size_t WN = (size_t)G3 * Hdim;
    auto Hf  = [&](int g, int p) { return h_p   + ((size_t)g * 2 + p) * HN; };
    auto Hhi = [&](int g, int p) { return ahi_p + ((size_t)g * 2 + p) * HN; };
    auto Hlo = [&](int g, int p) { return alo_p + ((size_t)g * 2 + p) * HN; };

    cudaFuncSetAttribute(gru_step_mma, cudaFuncAttributeMaxDynamicSharedMemorySize, DYN_SMEM);

    // weight splits + h0 init
    split_w_kernel<<<2048, 256>>>(g1wh, whi_p, wlo_p, (int)WN);
    split_w_kernel<<<2048, 256>>>(g2wh, whi_p + WN, wlo_p + WN, (int)WN);
    init_h_kernel<<<2048, 256>>>(context);

    // prologue (fp32 SIMT)
    gemm_bt_kernel<<<dim3(H2 / 64, Bsz / 64), 256>>>(context, wc, bc, ec_p, H2, Hdim, 1);
    gemm_bt_kernel<<<dim3(G3 / 64, Bsz / 64), 256>>>(ec_p, g1wi, g1bi, gi1_p, G3, H2, 0);
    gemm_bt_kernel<<<dim3(G3 / 64, Bsz / 64), 256>>>(ec_p, g2wi, g2bi, gi2_p, G3, H2, 0);

    const dim3 step_grid(Hdim / 64, Bsz / 128);   // 16 x 64 = 1024 CTAs
    for (int t = 0; t < T_PAST; t++) {
        int cur = t & 1;
        gru_step_mma<<<step_grid, 256, DYN_SMEM>>>(
            gi1_p, g1bh, whi_p, wlo_p,
            Hhi(0, cur), Hlo(0, cur), Hf(0, cur),
            Hf(0, cur ^ 1), Hhi(0, cur ^ 1), Hlo(0, cur ^ 1));
        proj4_kernel<<<Bsz / 4, 128>>>(Hf(0, cur ^ 1), fiw, fib, dec, t, T_PAST, 0);
        if (t < T_FUT) {
            gru_step_mma<<<step_grid, 256, DYN_SMEM>>>(
                gi2_p, g2bh, whi_p + WN, wlo_p + WN,
                Hhi(1, cur), Hlo(1, cur), Hf(1, cur),
                Hf(1, cur ^ 1), Hhi(1, cur ^ 1), Hlo(1, cur ^ 1));
            proj4_kernel<<<Bsz / 4, 128>>>(Hf(1, cur ^ 1), fow, fob, fut, t, T_FUT, 1);
        }
    }
}

// round 6
// speedup vs baseline: 2.1365x; 1.0634x over previous
#include <cuda_runtime.h>
#include <cuda_bf16.h>
#include <cstdint>
#include <math.h>

#define Bsz   8192
#define Hdim  1024
#define H2    512
#define G3    3072
#define T_PAST 60
#define T_FUT  30

// ---------------- scratch (static device globals) ----------------
__device__ float g_ec[Bsz * H2];
__device__ float g_gi1[Bsz * G3];
__device__ float g_gi2[Bsz * G3];
__device__ float g_h[2][2][Bsz * Hdim];                  // fp32 hidden, [gru][pp]
__device__ __nv_bfloat16 g_ahi[2][2][Bsz * Hdim];        // h split hi
__device__ __nv_bfloat16 g_alo[2][2][Bsz * Hdim];        // h split lo
__device__ __nv_bfloat16 g_whi[2][G3 * Hdim];            // wh split hi
__device__ __nv_bfloat16 g_wlo[2][G3 * Hdim];            // wh split lo
__device__ __nv_bfloat16 g_wihi[2][G3 * H2];             // wi split hi
__device__ __nv_bfloat16 g_wilo[2][G3 * H2];             // wi split lo
__device__ __nv_bfloat16 g_echi[Bsz * H2];               // ec split hi
__device__ __nv_bfloat16 g_eclo[Bsz * H2];               // ec split lo

// ---------------- PTX helpers (sm_80-level, compute_103-safe) ----------------
__device__ __forceinline__ uint32_t smem_u32(const void* p) {
    uint32_t a;
    asm("{ .reg .u64 t; cvta.to.shared.u64 t, %1; cvt.u32.u64 %0, t; }" : "=r"(a) : "l"(p));
    return a;
}
__device__ __forceinline__ void cp16(uint32_t s, const void* g) {
    asm volatile("cp.async.cg.shared.global [%0], [%1], 16;" :: "r"(s), "l"(g));
}
__device__ __forceinline__ void cp_commit() {
    asm volatile("cp.async.commit_group;" ::: "memory");
}
template <int N> __device__ __forceinline__ void cp_wait() {
    asm volatile("cp.async.wait_group %0;" :: "n"(N) : "memory");
}
__device__ __forceinline__ void ldsm_x4(uint32_t* r, uint32_t a) {
    asm volatile("ldmatrix.sync.aligned.m8n8.x4.shared.b16 {%0,%1,%2,%3}, [%4];"
                 : "=r"(r[0]), "=r"(r[1]), "=r"(r[2]), "=r"(r[3]) : "r"(a));
}
__device__ __forceinline__ void mma_bf16(float* c, const uint32_t* a, const uint32_t* b) {
    asm volatile(
        "mma.sync.aligned.m16n8k16.row.col.f32.bf16.bf16.f32 "
        "{%0,%1,%2,%3}, {%4,%5,%6,%7}, {%8,%9}, {%0,%1,%2,%3};"
        : "+f"(c[0]), "+f"(c[1]), "+f"(c[2]), "+f"(c[3])
        : "r"(a[0]), "r"(a[1]), "r"(a[2]), "r"(a[3]), "r"(b[0]), "r"(b[1]));
}

// ---------------- small kernels ----------------
__global__ void split_w_kernel(const float* __restrict__ src,
                               __nv_bfloat16* __restrict__ hi,
                               __nv_bfloat16* __restrict__ lo, int n) {
    int i = blockIdx.x * blockDim.x + threadIdx.x;
    int stride = gridDim.x * blockDim.x;
    for (; i < n; i += stride) {
        float f = src[i];
        __nv_bfloat16 h = __float2bfloat16(f);
        hi[i] = h;
        lo[i] = __float2bfloat16(f - __bfloat162float(h));
    }
}

__global__ void init_h_kernel(const float* __restrict__ ctx) {
    int i = blockIdx.x * blockDim.x + threadIdx.x;
    const int n = Bsz * Hdim;
    const int stride = gridDim.x * blockDim.x;
    for (; i < n; i += stride) {
        float v = ctx[i];
        __nv_bfloat16 h = __float2bfloat16(v);
        __nv_bfloat16 l = __float2bfloat16(v - __bfloat162float(h));
        g_h[0][0][i] = v;   g_h[1][0][i] = v;
        g_ahi[0][0][i] = h; g_ahi[1][0][i] = h;
        g_alo[0][0][i] = l; g_alo[1][0][i] = l;
    }
}

// fp32 SIMT GEMM for ec prologue only
__global__ void gemm_bt_kernel(const float* __restrict__ A,
                               const float* __restrict__ W,
                               const float* __restrict__ bias,
                               float* __restrict__ C,
                               int N, int K, int relu) {
    __shared__ float As[16][68];
    __shared__ float Bs[16][68];
    const int t   = threadIdx.x;
    const int tx  = t & 15, ty = t >> 4;
    const int m0  = blockIdx.y << 6, n0 = blockIdx.x << 6;
    const int lrow = t >> 2;
    const int lk   = (t & 3) << 2;

    float acc[4][4] = {};
    const float* Ap = A + (size_t)(m0 + lrow) * K + lk;
    const float* Wp = W + (size_t)(n0 + lrow) * K + lk;

    for (int k0 = 0; k0 < K; k0 += 16) {
        float4 a = *(const float4*)(Ap + k0);
        float4 b = *(const float4*)(Wp + k0);
        __syncthreads();
        As[lk + 0][lrow] = a.x; As[lk + 1][lrow] = a.y;
        As[lk + 2][lrow] = a.z; As[lk + 3][lrow] = a.w;
        Bs[lk + 0][lrow] = b.x; Bs[lk + 1][lrow] = b.y;
        Bs[lk + 2][lrow] = b.z; Bs[lk + 3][lrow] = b.w;
        __syncthreads();
#pragma unroll
        for (int k = 0; k < 16; k++) {
            float4 av = *(const float4*)&As[k][ty << 2];
            float4 bv = *(const float4*)&Bs[k][tx << 2];
            float aa[4] = {av.x, av.y, av.z, av.w};
            float bb[4] = {bv.x, bv.y, bv.z, bv.w};
#pragma unroll
            for (int i = 0; i < 4; i++)
#pragma unroll
                for (int j = 0; j < 4; j++)
                    acc[i][j] += aa[i] * bb[j];
        }
    }
#pragma unroll
    for (int i = 0; i < 4; i++) {
        int m = m0 + (ty << 2) + i;
#pragma unroll
        for (int j = 0; j < 4; j++) {
            int n = n0 + (tx << 2) + j;
            float v = acc[i][j] + bias[n];
            if (relu) v = fmaxf(v, 0.0f);
            C[(size_t)m * N + n] = v;
        }
    }
}

// ---------------- HMMA 3-gate GEMM (M_TILE=64, 2 CTAs/SM) ----------------
static constexpr int OFF_ALO   = 64 * 48;                // 3072
static constexpr int OFF_WHI   = 2 * 64 * 48;            // 6144
static constexpr int WLODELTA  = 192 * 48;               // 9216
static constexpr int STAGE     = OFF_WHI + 2 * 192 * 48; // 24576
static constexpr int NS        = 4;
static constexpr int DYN_SMEM  = NS * STAGE;             // 98304

struct GemmArgs {
    const __nv_bfloat16 *ahi, *alo, *whi, *wlo;
    const float* bias;     // [3*1024] layout (bh or bi)
    const float* gi;       // MODE 0
    const float* hin;      // MODE 0
    float*       hout;     // MODE 0
    __nv_bfloat16 *ohi, *olo;  // MODE 0
    float*       giout;    // MODE 1
    int          lda;      // row stride (elems) of A and W
};

// MODE 0: fused GRU step (K = 1024).  MODE 1: gi GEMM + bias (K = lda*? passed via K16)
template <int MODE, int K16>
__global__ void __launch_bounds__(256, 2)
hmma3_kernel(GemmArgs arg0, GemmArgs arg1) {
    extern __shared__ char dsmem[];
    __shared__ float s_bh[192];

    const GemmArgs& A = (blockIdx.z == 0) ? arg0 : arg1;

    const int t   = threadIdx.x;
    const int wid = t >> 5, L = t & 31;
    const int n0  = blockIdx.x * 64;     // per-gate column tile
    const int m0  = blockIdx.y * 64;     // batch tile
    const int mwarp = wid >> 1, nwarp = wid & 1;
    const int lda = A.lda;

    const uint32_t dynb = smem_u32(dsmem);

    if (t < 192) s_bh[t] = A.bias[(t >> 6) * 1024 + n0 + (t & 63)];

    // ---- cp.async chunk assignment ----
    // A: 256 chunks: which = t>>7, row = (t>>1)&63, half = t&1
    const int arow = (t >> 1) & 63, ahalf = t & 1, awhich = t >> 7;
    const __nv_bfloat16* srcA =
        (awhich ? A.alo : A.ahi) + (size_t)(m0 + arow) * lda + 8 * ahalf;
    const uint32_t dstA = (uint32_t)(awhich * OFF_ALO + arow * 48 + ahalf * 16);

    // W: 768 chunks, 3 per thread
    const __nv_bfloat16* srcW[3];
    uint32_t dstW[3];
#pragma unroll
    for (int j = 0; j < 3; j++) {
        int c = t + 256 * j;
        int half = c & 1;
        int r2 = c >> 1;              // 0..383
        int which = (r2 >= 192);
        int wr = r2 - which * 192;    // 0..191
        int g = wr >> 6, n = wr & 63;
        srcW[j] = (which ? A.wlo : A.whi) + (size_t)(g * 1024 + n0 + n) * lda + 8 * half;
        dstW[j] = (uint32_t)(OFF_WHI + which * WLODELTA + wr * 48 + half * 16);
    }

    auto load_stage = [&](uint32_t base, int ke) {
        cp16(base + dstA, srcA + ke);
        cp16(base + dstW[0], srcW[0] + ke);
        cp16(base + dstW[1], srcW[1] + ke);
        cp16(base + dstW[2], srcW[2] + ke);
    };

    // ---- ldmatrix lane offsets ----
    const uint32_t aoff = (uint32_t)((mwarp * 16 + (L & 15)) * 48 + (L >> 4) * 16);
    uint32_t boff[3][2];
    {
        int nlane = (L & 7) + ((L & 16) ? 8 : 0);
        int k8 = (L >> 3) & 1;
#pragma unroll
        for (int g = 0; g < 3; g++)
#pragma unroll
            for (int u = 0; u < 2; u++)
                boff[g][u] = (uint32_t)(OFF_WHI +
                    (g * 64 + nwarp * 32 + u * 16 + nlane) * 48 + k8 * 16);
    }

    // ---- pipeline prologue ----
#pragma unroll
    for (int s = 0; s < NS - 1; s++) {
        load_stage(dynb + s * STAGE, s * 16);
        cp_commit();
    }

    float acc[3][4][4];
#pragma unroll
    for (int g = 0; g < 3; g++)
#pragma unroll
        for (int nt = 0; nt < 4; nt++)
#pragma unroll
            for (int e = 0; e < 4; e++) acc[g][nt][e] = 0.0f;

    // ---- main K loop ----
#pragma unroll 1
    for (int ki = 0; ki < K16; ki++) {
        cp_wait<NS - 2>();
        __syncthreads();
        const uint32_t sb = dynb + (uint32_t)(ki & (NS - 1)) * STAGE;

        uint32_t AH[4], AL[4];
        ldsm_x4(AH, sb + aoff);
        ldsm_x4(AL, sb + aoff + OFF_ALO);
#pragma unroll
        for (int g = 0; g < 3; g++) {
            uint32_t BH[2][4], BL[2][4];
            ldsm_x4(BH[0], sb + boff[g][0]);
            ldsm_x4(BH[1], sb + boff[g][1]);
            ldsm_x4(BL[0], sb + boff[g][0] + WLODELTA);
            ldsm_x4(BL[1], sb + boff[g][1] + WLODELTA);
#pragma unroll
            for (int nt = 0; nt < 4; nt++) {
                const uint32_t* bhp = &BH[nt >> 1][(nt & 1) * 2];
                const uint32_t* blp = &BL[nt >> 1][(nt & 1) * 2];
                mma_bf16(acc[g][nt], AH, bhp);
                mma_bf16(acc[g][nt], AH, blp);
                mma_bf16(acc[g][nt], AL, bhp);
            }
        }

        const int kn = ki + NS - 1;
        if (kn < K16) load_stage(dynb + (uint32_t)(kn & (NS - 1)) * STAGE, kn * 16);
        cp_commit();
    }

    // ---- epilogue ----
    const int rq = L >> 2, cq = L & 3;
#pragma unroll
    for (int rs = 0; rs < 2; rs++) {
        const int row = m0 + mwarp * 16 + rs * 8 + rq;
        if (MODE == 1) {
            float* go = A.giout + (size_t)row * G3;
#pragma unroll
            for (int g = 0; g < 3; g++)
#pragma unroll
                for (int nt = 0; nt < 4; nt++) {
                    const int c = nwarp * 32 + nt * 8 + 2 * cq;
                    float v0 = acc[g][nt][rs * 2 + 0] + s_bh[g * 64 + c];
                    float v1 = acc[g][nt][rs * 2 + 1] + s_bh[g * 64 + c + 1];
                    *(float2*)(go + g * 1024 + n0 + c) = make_float2(v0, v1);
                }
        } else {
            const float* gib  = A.gi  + (size_t)row * G3;
            const float* hinr = A.hin + (size_t)row * Hdim;
            float*       hor  = A.hout + (size_t)row * Hdim;
            __nv_bfloat16* hhr = A.ohi + (size_t)row * Hdim;
            __nv_bfloat16* hlr = A.olo + (size_t)row * Hdim;
#pragma unroll
            for (int nt = 0; nt < 4; nt++) {
                const int c   = nwarp * 32 + nt * 8 + 2 * cq;
                const int col = n0 + c;
                float2 ir  = *(const float2*)(gib + col);
                float2 iz  = *(const float2*)(gib + 1024 + col);
                float2 inn = *(const float2*)(gib + 2048 + col);
                float2 hv  = *(const float2*)(hinr + col);
                float ira[2] = {ir.x, ir.y};
                float iza[2] = {iz.x, iz.y};
                float ina[2] = {inn.x, inn.y};
                float hva[2] = {hv.x, hv.y};
                float o[2];
#pragma unroll
                for (int e = 0; e < 2; e++) {
                    float hr = acc[0][nt][rs * 2 + e] + s_bh[c + e];
                    float hz = acc[1][nt][rs * 2 + e] + s_bh[64 + c + e];
                    float hn = acc[2][nt][rs * 2 + e] + s_bh[128 + c + e];
                    float r = 1.0f / (1.0f + __expf(-(ira[e] + hr)));
                    float z = 1.0f / (1.0f + __expf(-(iza[e] + hz)));
                    float ex = __expf(2.0f * (ina[e] + r * hn));
                    float nn = 1.0f - 2.0f / (ex + 1.0f);
                    o[e] = (1.0f - z) * nn + z * hva[e];
                }
                *(float2*)(hor + col) = make_float2(o[0], o[1]);
                __nv_bfloat16 h0 = __float2bfloat16(o[0]);
                __nv_bfloat16 h1 = __float2bfloat16(o[1]);
                *(__nv_bfloat162*)(hhr + col) = __nv_bfloat162(h0, h1);
                *(__nv_bfloat162*)(hlr + col) = __nv_bfloat162(
                    __float2bfloat16(o[0] - __bfloat162float(h0)),
                    __float2bfloat16(o[1] - __bfloat162float(h1)));
            }
        }
    }
}

// ---------------- per-step 4-col projection (dual via blockIdx.y) ----------------
struct ProjArgs {
    const float* h;
    const float* w;
    const float* bias;
    float* out;
    int tstep, T, relu;
};

__global__ void proj4_dual(ProjArgs p0, ProjArgs p1) {
    const ProjArgs& P = (blockIdx.y == 0) ? p0 : p1;
    __shared__ float ws[4 * Hdim];
    const int tid = threadIdx.x;
    for (int i = tid * 4; i < 4 * Hdim; i += blockDim.x * 4)
        *(float4*)&ws[i] = *(const float4*)(P.w + i);
    __syncthreads();

    const int warp = tid >> 5, lane = tid & 31;
    const int b = blockIdx.x * 4 + warp;
    const float* hrow = P.h + (size_t)b * Hdim;

    float a0 = 0.f, a1 = 0.f, a2 = 0.f, a3 = 0.f;
    for (int j = lane; j < Hdim; j += 32) {
        float hv = hrow[j];
        if (P.relu) hv = fmaxf(hv, 0.0f);
        a0 += hv * ws[j];
        a1 += hv * ws[Hdim + j];
        a2 += hv * ws[2 * Hdim + j];
        a3 += hv * ws[3 * Hdim + j];
    }
#pragma unroll
    for (int off = 16; off; off >>= 1) {
        a0 += __shfl_down_sync(0xffffffffu, a0, off);
        a1 += __shfl_down_sync(0xffffffffu, a1, off);
        a2 += __shfl_down_sync(0xffffffffu, a2, off);
        a3 += __shfl_down_sync(0xffffffffu, a3, off);
    }
    if (lane == 0) {
        float* o = P.out + (size_t)b * P.T * 4 + (size_t)P.tstep * 4;
        o[0] = a0 + P.bias[0];
        o[1] = a1 + P.bias[1];
        o[2] = a2 + P.bias[2];
        o[3] = a3 + P.bias[3];
    }
}

// ---------------------------------------------------------------------------
extern "C" void kernel_launch(void* const* d_in, const int* in_sizes, int n_in,
                              void* d_out, int out_size) {
    const float* context = (const float*)d_in[0];
    const float* wc      = (const float*)d_in[1];
    const float* bc      = (const float*)d_in[2];
    const float* g1wi    = (const float*)d_in[3];
    const float* g1wh    = (const float*)d_in[4];
    const float* g1bi    = (const float*)d_in[5];
    const float* g1bh    = (const float*)d_in[6];
    const float* g2wi    = (const float*)d_in[7];
    const float* g2wh    = (const float*)d_in[8];
    const float* g2bi    = (const float*)d_in[9];
    const float* g2bh    = (const float*)d_in[10];
    const float* fiw     = (const float*)d_in[11];
    const float* fib     = (const float*)d_in[12];
    const float* fow     = (const float*)d_in[13];
    const float* fob     = (const float*)d_in[14];

    float* dec = (float*)d_out;
    float* fut = (float*)d_out + (size_t)Bsz * T_PAST * 4;

    float *ec_p, *gi1_p, *gi2_p, *h_p;
    __nv_bfloat16 *ahi_p, *alo_p, *whi_p, *wlo_p, *wihi_p, *wilo_p, *echi_p, *eclo_p;
    cudaGetSymbolAddress((void**)&ec_p,   g_ec);
    cudaGetSymbolAddress((void**)&gi1_p,  g_gi1);
    cudaGetSymbolAddress((void**)&gi2_p,  g_gi2);
    cudaGetSymbolAddress((void**)&h_p,    g_h);
    cudaGetSymbolAddress((void**)&ahi_p,  g_ahi);
    cudaGetSymbolAddress((void**)&alo_p,  g_alo);
    cudaGetSymbolAddress((void**)&whi_p,  g_whi);
    cudaGetSymbolAddress((void**)&wlo_p,  g_wlo);
    cudaGetSymbolAddress((void**)&wihi_p, g_wihi);
    cudaGetSymbolAddress((void**)&wilo_p, g_wilo);
    cudaGetSymbolAddress((void**)&echi_p, g_echi);
    cudaGetSymbolAddress((void**)&eclo_p, g_eclo);

    const size_t HN  = (size_t)Bsz * Hdim;
    const size_t WN  = (size_t)G3 * Hdim;
    const size_t WIN = (size_t)G3 * H2;
    auto Hf  = [&](int g, int p) { return h_p   + ((size_t)g * 2 + p) * HN; };
    auto Hhi = [&](int g, int p) { return ahi_p + ((size_t)g * 2 + p) * HN; };
    auto Hlo = [&](int g, int p) { return alo_p + ((size_t)g * 2 + p) * HN; };

    cudaFuncSetAttribute(hmma3_kernel<0, 64>, cudaFuncAttributeMaxDynamicSharedMemorySize, DYN_SMEM);
    cudaFuncSetAttribute(hmma3_kernel<1, 32>, cudaFuncAttributeMaxDynamicSharedMemorySize, DYN_SMEM);

    // ---- prologue ----
    // ec = relu(context @ wc^T + bc)   (fp32 SIMT)
    gemm_bt_kernel<<<dim3(H2 / 64, Bsz / 64), 256>>>(context, wc, bc, ec_p, H2, Hdim, 1);
    // splits
    split_w_kernel<<<2048, 256>>>(g1wh, whi_p, wlo_p, (int)WN);
    split_w_kernel<<<2048, 256>>>(g2wh, whi_p + WN, wlo_p + WN, (int)WN);
    split_w_kernel<<<1024, 256>>>(g1wi, wihi_p, wilo_p, (int)WIN);
    split_w_kernel<<<1024, 256>>>(g2wi, wihi_p + WIN, wilo_p + WIN, (int)WIN);
    split_w_kernel<<<1024, 256>>>(ec_p, echi_p, eclo_p, Bsz * H2);
    init_h_kernel<<<2048, 256>>>(context);

    // gi = ec @ wi^T + bi  (HMMA, both GRUs in one launch)
    {
        GemmArgs a0 = {}, a1 = {};
        a0.ahi = echi_p; a0.alo = eclo_p; a0.whi = wihi_p; a0.wlo = wilo_p;
        a0.bias = g1bi;  a0.giout = gi1_p; a0.lda = H2;
        a1 = a0;
        a1.whi = wihi_p + WIN; a1.wlo = wilo_p + WIN;
        a1.bias = g2bi; a1.giout = gi2_p;
        hmma3_kernel<1, 32><<<dim3(16, Bsz / 64, 2), 256, DYN_SMEM>>>(a0, a1);
    }

    // ---- recurrent steps ----
    for (int t = 0; t < T_PAST; t++) {
        const int cur = t & 1;
        GemmArgs a0 = {}, a1 = {};
        a0.ahi = Hhi(0, cur); a0.alo = Hlo(0, cur);
        a0.whi = whi_p; a0.wlo = wlo_p; a0.bias = g1bh;
        a0.gi = gi1_p; a0.hin = Hf(0, cur); a0.hout = Hf(0, cur ^ 1);
        a0.ohi = Hhi(0, cur ^ 1); a0.olo = Hlo(0, cur ^ 1); a0.lda = Hdim;
        const int z = (t < T_FUT) ? 2 : 1;
        if (t < T_FUT) {
            a1.ahi = Hhi(1, cur); a1.alo = Hlo(1, cur);
            a1.whi = whi_p + WN; a1.wlo = wlo_p + WN; a1.bias = g2bh;
            a1.gi = gi2_p; a1.hin = Hf(1, cur); a1.hout = Hf(1, cur ^ 1);
            a1.ohi = Hhi(1, cur ^ 1); a1.olo = Hlo(1, cur ^ 1); a1.lda = Hdim;
        }
        hmma3_kernel<0, 64><<<dim3(16, Bsz / 64, z), 256, DYN_SMEM>>>(a0, a1);

        ProjArgs p0 = {Hf(0, cur ^ 1), fiw, fib, dec, t, T_PAST, 0};
        ProjArgs p1 = {Hf(1, cur ^ 1), fow, fob, fut, t, T_FUT, 1};
        proj4_dual<<<dim3(Bsz / 4, z), 128>>>(p0, p1);
    }
}

// round 8
// speedup vs baseline: 3.6421x; 1.7047x over previous
#include <cuda_runtime.h>
#include <cuda_fp16.h>
#include <cstdint>
#include <math.h>

#define Bsz   8192
#define Hdim  1024
#define H2    512
#define G3    3072
#define T_PAST 60
#define T_FUT  30

// ---------------- scratch (static device globals) ----------------
__device__ float g_ec[Bsz * H2];
__device__ float g_gi1[Bsz * G3];
__device__ float g_gi2[Bsz * G3];
__device__ float g_h[2][2][Bsz * Hdim];          // fp32 hidden, [gru][pp]
__device__ __half g_ah[2][2][Bsz * Hdim];        // h as fp16, [gru][pp]
__device__ __half g_wh16[2][G3 * Hdim];          // wh fp16
__device__ __half g_wi16[2][G3 * H2];            // wi fp16
__device__ __half g_ec16[Bsz * H2];              // ec fp16

// ---------------- PTX helpers (sm_80-level, compute_103-safe) ----------------
__device__ __forceinline__ uint32_t smem_u32(const void* p) {
    uint32_t a;
    asm("{ .reg .u64 t; cvta.to.shared.u64 t, %1; cvt.u32.u64 %0, t; }" : "=r"(a) : "l"(p));
    return a;
}
__device__ __forceinline__ void cp16(uint32_t s, const void* g) {
    asm volatile("cp.async.cg.shared.global [%0], [%1], 16;" :: "r"(s), "l"(g));
}
__device__ __forceinline__ void cp_commit() {
    asm volatile("cp.async.commit_group;" ::: "memory");
}
template <int N> __device__ __forceinline__ void cp_wait() {
    asm volatile("cp.async.wait_group %0;" :: "n"(N) : "memory");
}
__device__ __forceinline__ void ldsm_x4(uint32_t* r, uint32_t a) {
    asm volatile("ldmatrix.sync.aligned.m8n8.x4.shared.b16 {%0,%1,%2,%3}, [%4];"
                 : "=r"(r[0]), "=r"(r[1]), "=r"(r[2]), "=r"(r[3]) : "r"(a));
}
__device__ __forceinline__ void mma_f16(float* c, const uint32_t* a, const uint32_t* b) {
    asm volatile(
        "mma.sync.aligned.m16n8k16.row.col.f32.f16.f16.f32 "
        "{%0,%1,%2,%3}, {%4,%5,%6,%7}, {%8,%9}, {%0,%1,%2,%3};"
        : "+f"(c[0]), "+f"(c[1]), "+f"(c[2]), "+f"(c[3])
        : "r"(a[0]), "r"(a[1]), "r"(a[2]), "r"(a[3]), "r"(b[0]), "r"(b[1]));
}

// ---------------- small kernels ----------------
__global__ void f2h_kernel(const float* __restrict__ src, __half* __restrict__ dst, int n) {
    int i = blockIdx.x * blockDim.x + threadIdx.x;
    int stride = gridDim.x * blockDim.x;
    for (; i < n; i += stride) dst[i] = __float2half(src[i]);
}

__global__ void init_h_kernel(const float* __restrict__ ctx) {
    int i = blockIdx.x * blockDim.x + threadIdx.x;
    const int n = Bsz * Hdim;
    const int stride = gridDim.x * blockDim.x;
    for (; i < n; i += stride) {
        float v = ctx[i];
        __half h = __float2half(v);
        g_h[0][0][i] = v;  g_h[1][0][i] = v;
        g_ah[0][0][i] = h; g_ah[1][0][i] = h;
    }
}

// fp32 SIMT GEMM for ec prologue only
__global__ void gemm_bt_kernel(const float* __restrict__ A,
                               const float* __restrict__ W,
                               const float* __restrict__ bias,
                               float* __restrict__ C,
                               int N, int K, int relu) {
    __shared__ float As[16][68];
    __shared__ float Bs[16][68];
    const int t   = threadIdx.x;
    const int tx  = t & 15, ty = t >> 4;
    const int m0  = blockIdx.y << 6, n0 = blockIdx.x << 6;
    const int lrow = t >> 2;
    const int lk   = (t & 3) << 2;

    float acc[4][4] = {};
    const float* Ap = A + (size_t)(m0 + lrow) * K + lk;
    const float* Wp = W + (size_t)(n0 + lrow) * K + lk;

    for (int k0 = 0; k0 < K; k0 += 16) {
        float4 a = *(const float4*)(Ap + k0);
        float4 b = *(const float4*)(Wp + k0);
        __syncthreads();
        As[lk + 0][lrow] = a.x; As[lk + 1][lrow] = a.y;
        As[lk + 2][lrow] = a.z; As[lk + 3][lrow] = a.w;
        Bs[lk + 0][lrow] = b.x; Bs[lk + 1][lrow] = b.y;
        Bs[lk + 2][lrow] = b.z; Bs[lk + 3][lrow] = b.w;
        __syncthreads();
#pragma unroll
        for (int k = 0; k < 16; k++) {
            float4 av = *(const float4*)&As[k][ty << 2];
            float4 bv = *(const float4*)&Bs[k][tx << 2];
            float aa[4] = {av.x, av.y, av.z, av.w};
            float bb[4] = {bv.x, bv.y, bv.z, bv.w};
#pragma unroll
            for (int i = 0; i < 4; i++)
#pragma unroll
                for (int j = 0; j < 4; j++)
                    acc[i][j] += aa[i] * bb[j];
        }
    }
#pragma unroll
    for (int i = 0; i < 4; i++) {
        int m = m0 + (ty << 2) + i;
#pragma unroll
        for (int j = 0; j < 4; j++) {
            int n = n0 + (tx << 2) + j;
            float v = acc[i][j] + bias[n];
            if (relu) v = fmaxf(v, 0.0f);
            C[(size_t)m * N + n] = v;
        }
    }
}

// ---------------- single-term fp16 HMMA 3-gate GEMM ----------------
// CTA: 256 thr / 8 warps (2 m-warps x 4 n-warps). Tile: M=64, N=64 per gate x3.
// smem stage: A 64 rows x 48B + W 192 rows x 48B = 12,288 B. NS=4 -> 48 KB, 2 CTAs/SM.
static constexpr int OFF_W    = 64 * 48;                 // 3072
static constexpr int STAGE    = OFF_W + 192 * 48;        // 12288
static constexpr int NS       = 4;
static constexpr int DYN_SMEM = NS * STAGE;              // 49152

struct GemmArgs {
    const __half *a16, *w16;
    const float* bias;         // [3*1024]
    const float* gi;           // MODE 0
    const float* hin;          // MODE 0
    float*       hout;         // MODE 0
    __half*      oh;           // MODE 0
    float*       giout;        // MODE 1
    int          lda;          // row stride (elems) of A and W
};

// MODE 0: fused GRU step (K16=64).  MODE 1: gi GEMM + bias (K16=32)
template <int MODE, int K16>
__global__ void __launch_bounds__(256, 2)
hmma1_kernel(GemmArgs arg0, GemmArgs arg1) {
    extern __shared__ char dsmem[];
    __shared__ float s_bh[192];

    const GemmArgs& A = (blockIdx.z == 0) ? arg0 : arg1;

    const int t   = threadIdx.x;
    const int wid = t >> 5, L = t & 31;
    const int n0  = blockIdx.x * 64;     // per-gate column tile
    const int m0  = blockIdx.y * 64;     // batch tile
    const int mwarp = wid >> 2, nwarp = wid & 3;
    const int lda = A.lda;

    const uint32_t dynb = smem_u32(dsmem);

    if (t < 192) s_bh[t] = A.bias[(t >> 6) * 1024 + n0 + (t & 63)];

    // ---- cp.async chunk assignment: 512 x 16B chunks per stage, 2 per thread ----
    const __half* src[2];
    uint32_t dst[2];
#pragma unroll
    for (int j = 0; j < 2; j++) {
        int c = t + 256 * j;
        if (c < 128) {                       // A: 64 rows x 2 halves
            int row = c >> 1, half = c & 1;
            src[j] = A.a16 + (size_t)(m0 + row) * lda + 8 * half;
            dst[j] = (uint32_t)(row * 48 + half * 16);
        } else {                             // W: 192 rows x 2 halves
            int cw = c - 128;
            int row = cw >> 1, half = cw & 1;
            int g = row >> 6, n = row & 63;
            src[j] = A.w16 + (size_t)(g * 1024 + n0 + n) * lda + 8 * half;
            dst[j] = (uint32_t)(OFF_W + row * 48 + half * 16);
        }
    }

    auto load_stage = [&](uint32_t base, int ke) {
        cp16(base + dst[0], src[0] + ke);
        cp16(base + dst[1], src[1] + ke);
    };

    // ---- ldmatrix lane offsets ----
    const uint32_t aoff = (uint32_t)((mwarp * 32 + (L & 15)) * 48 + (L >> 4) * 16);
    uint32_t boff[3];
    {
        int nlane = (L & 7) + ((L & 16) ? 8 : 0);
        int k8 = (L >> 3) & 1;
#pragma unroll
        for (int g = 0; g < 3; g++)
            boff[g] = (uint32_t)(OFF_W + (g * 64 + nwarp * 16 + nlane) * 48 + k8 * 16);
    }

    // ---- pipeline prologue ----
#pragma unroll
    for (int s = 0; s < NS - 1; s++) {
        load_stage(dynb + s * STAGE, s * 16);
        cp_commit();
    }

    float acc[3][2][2][4];   // [gate][m16][n8][4]
#pragma unroll
    for (int g = 0; g < 3; g++)
#pragma unroll
        for (int mt = 0; mt < 2; mt++)
#pragma unroll
            for (int nt = 0; nt < 2; nt++)
#pragma unroll
                for (int e = 0; e < 4; e++) acc[g][mt][nt][e] = 0.0f;

    // ---- main K loop ----
#pragma unroll 1
    for (int ki = 0; ki < K16; ki++) {
        cp_wait<NS - 2>();
        __syncthreads();
        const uint32_t sb = dynb + (uint32_t)(ki & (NS - 1)) * STAGE;

        uint32_t A0[4], A1[4];
        ldsm_x4(A0, sb + aoff);
        ldsm_x4(A1, sb + aoff + 16 * 48);
#pragma unroll
        for (int g = 0; g < 3; g++) {
            uint32_t B[4];
            ldsm_x4(B, sb + boff[g]);
            mma_f16(acc[g][0][0], A0, &B[0]);
            mma_f16(acc[g][0][1], A0, &B[2]);
            mma_f16(acc[g][1][0], A1, &B[0]);
            mma_f16(acc[g][1][1], A1, &B[2]);
        }

        const int kn = ki + NS - 1;
        if (kn < K16) load_stage(dynb + (uint32_t)(kn & (NS - 1)) * STAGE, kn * 16);
        cp_commit();
    }

    // ---- epilogue ----
    const int rq = L >> 2, cq = L & 3;
#pragma unroll
    for (int mt = 0; mt < 2; mt++) {
#pragma unroll
        for (int rs = 0; rs < 2; rs++) {
            const int row = m0 + mwarp * 32 + mt * 16 + rs * 8 + rq;
            if (MODE == 1) {
                float* go = A.giout + (size_t)row * G3;
#pragma unroll
                for (int g = 0; g < 3; g++)
#pragma unroll
                    for (int nt = 0; nt < 2; nt++) {
                        const int c = nwarp * 16 + nt * 8 + 2 * cq;
                        float v0 = acc[g][mt][nt][rs * 2 + 0] + s_bh[g * 64 + c];
                        float v1 = acc[g][mt][nt][rs * 2 + 1] + s_bh[g * 64 + c + 1];
                        *(float2*)(go + g * 1024 + n0 + c) = make_float2(v0, v1);
                    }
            } else {
                const float* gib  = A.gi  + (size_t)row * G3;
                const float* hinr = A.hin + (size_t)row * Hdim;
                float*       hor  = A.hout + (size_t)row * Hdim;
                __half*      hhr  = A.oh  + (size_t)row * Hdim;
#pragma unroll
                for (int nt = 0; nt < 2; nt++) {
                    const int c   = nwarp * 16 + nt * 8 + 2 * cq;
                    const int col = n0 + c;
                    float2 ir  = *(const float2*)(gib + col);
                    float2 iz  = *(const float2*)(gib + 1024 + col);
                    float2 inn = *(const float2*)(gib + 2048 + col);
                    float2 hv  = *(const float2*)(hinr + col);
                    float ira[2] = {ir.x, ir.y};
                    float iza[2] = {iz.x, iz.y};
                    float ina[2] = {inn.x, inn.y};
                    float hva[2] = {hv.x, hv.y};
                    float o[2];
#pragma unroll
                    for (int e = 0; e < 2; e++) {
                        float hr = acc[0][mt][nt][rs * 2 + e] + s_bh[c + e];
                        float hz = acc[1][mt][nt][rs * 2 + e] + s_bh[64 + c + e];
                        float hn = acc[2][mt][nt][rs * 2 + e] + s_bh[128 + c + e];
                        float r = 1.0f / (1.0f + __expf(-(ira[e] + hr)));
                        float z = 1.0f / (1.0f + __expf(-(iza[e] + hz)));
                        float ex = __expf(2.0f * (ina[e] + r * hn));
                        float nn = 1.0f - 2.0f / (ex + 1.0f);
                        o[e] = (1.0f - z) * nn + z * hva[e];
                    }
                    *(float2*)(hor + col) = make_float2(o[0], o[1]);
                    *(__half2*)(hhr + col) = __half2(__float2half(o[0]), __float2half(o[1]));
                }
            }
        }
    }
}

// ---------------- per-step 4-col projection (dual via blockIdx.y) ----------------
struct ProjArgs {
    const float* h;
    const float* w;
    const float* bias;
    float* out;
    int tstep, T, relu;
};

__global__ void proj4_dual(ProjArgs p0, ProjArgs p1) {
    const ProjArgs& P = (blockIdx.y == 0) ? p0 : p1;
    __shared__ float ws[4 * Hdim];
    const int tid = threadIdx.x;
    for (int i = tid * 4; i < 4 * Hdim; i += blockDim.x * 4)
        *(float4*)&ws[i] = *(const float4*)(P.w + i);
    __syncthreads();

    const int warp = tid >> 5, lane = tid & 31;
    const int b = blockIdx.x * 4 + warp;
    const float* hrow = P.h + (size_t)b * Hdim;

    float a0 = 0.f, a1 = 0.f, a2 = 0.f, a3 = 0.f;
    for (int j = lane; j < Hdim; j += 32) {
        float hv = hrow[j];
        if (P.relu) hv = fmaxf(hv, 0.0f);
        a0 += hv * ws[j];
        a1 += hv * ws[Hdim + j];
        a2 += hv * ws[2 * Hdim + j];
        a3 += hv * ws[3 * Hdim + j];
    }
#pragma unroll
    for (int off = 16; off; off >>= 1) {
        a0 += __shfl_down_sync(0xffffffffu, a0, off);
        a1 += __shfl_down_sync(0xffffffffu, a1, off);
        a2 += __shfl_down_sync(0xffffffffu, a2, off);
        a3 += __shfl_down_sync(0xffffffffu, a3, off);
    }
    if (lane == 0) {
        float* o = P.out + (size_t)b * P.T * 4 + (size_t)P.tstep * 4;
        o[0] = a0 + P.bias[0];
        o[1] = a1 + P.bias[1];
        o[2] = a2 + P.bias[2];
        o[3] = a3 + P.bias[3];
    }
}

// ---------------------------------------------------------------------------
extern "C" void kernel_launch(void* const* d_in, const int* in_sizes, int n_in,
                              void* d_out, int out_size) {
    const float* context = (const float*)d_in[0];
    const float* wc      = (const float*)d_in[1];
    const float* bc      = (const float*)d_in[2];
    const float* g1wi    = (const float*)d_in[3];
    const float* g1wh    = (const float*)d_in[4];
    const float* g1bi    = (const float*)d_in[5];
    const float* g1bh    = (const float*)d_in[6];
    const float* g2wi    = (const float*)d_in[7];
    const float* g2wh    = (const float*)d_in[8];
    const float* g2bi    = (const float*)d_in[9];
    const float* g2bh    = (const float*)d_in[10];
    const float* fiw     = (const float*)d_in[11];
    const float* fib     = (const float*)d_in[12];
    const float* fow     = (const float*)d_in[13];
    const float* fob     = (const float*)d_in[14];

    float* dec = (float*)d_out;
    float* fut = (float*)d_out + (size_t)Bsz * T_PAST * 4;

    float *ec_p, *gi1_p, *gi2_p, *h_p;
    __half *ah_p, *wh16_p, *wi16_p, *ec16_p;
    cudaGetSymbolAddress((void**)&ec_p,   g_ec);
    cudaGetSymbolAddress((void**)&gi1_p,  g_gi1);
    cudaGetSymbolAddress((void**)&gi2_p,  g_gi2);
    cudaGetSymbolAddress((void**)&h_p,    g_h);
    cudaGetSymbolAddress((void**)&ah_p,   g_ah);
    cudaGetSymbolAddress((void**)&wh16_p, g_wh16);
    cudaGetSymbolAddress((void**)&wi16_p, g_wi16);
    cudaGetSymbolAddress((void**)&ec16_p, g_ec16);

    const size_t HN  = (size_t)Bsz * Hdim;
    const size_t WN  = (size_t)G3 * Hdim;
    const size_t WIN = (size_t)G3 * H2;
    auto Hf  = [&](int g, int p) { return h_p  + ((size_t)g * 2 + p) * HN; };
    auto Hh  = [&](int g, int p) { return ah_p + ((size_t)g * 2 + p) * HN; };

    cudaFuncSetAttribute(hmma1_kernel<0, 64>, cudaFuncAttributeMaxDynamicSharedMemorySize, DYN_SMEM);
    cudaFuncSetAttribute(hmma1_kernel<1, 32>, cudaFuncAttributeMaxDynamicSharedMemorySize, DYN_SMEM);

    // ---- prologue ----
    gemm_bt_kernel<<<dim3(H2 / 64, Bsz / 64), 256>>>(context, wc, bc, ec_p, H2, Hdim, 1);
    f2h_kernel<<<2048, 256>>>(g1wh, wh16_p, (int)WN);
    f2h_kernel<<<2048, 256>>>(g2wh, wh16_p + WN, (int)WN);
    f2h_kernel<<<1024, 256>>>(g1wi, wi16_p, (int)WIN);
    f2h_kernel<<<1024, 256>>>(g2wi, wi16_p + WIN, (int)WIN);
    f2h_kernel<<<1024, 256>>>(ec_p, ec16_p, Bsz * H2);
    init_h_kernel<<<2048, 256>>>(context);

    // gi = ec @ wi^T + bi  (HMMA, both GRUs in one launch)
    {
        GemmArgs a0 = {}, a1 = {};
        a0.a16 = ec16_p; a0.w16 = wi16_p; a0.bias = g1bi; a0.giout = gi1_p; a0.lda = H2;
        a1 = a0;
        a1.w16 = wi16_p + WIN; a1.bias = g2bi; a1.giout = gi2_p;
        hmma1_kernel<1, 32><<<dim3(16, Bsz / 64, 2), 256, DYN_SMEM>>>(a0, a1);
    }

    // ---- recurrent steps ----
    for (int t = 0; t < T_PAST; t++) {
        const int cur = t & 1;
        GemmArgs a0 = {}, a1 = {};
        a0.a16 = Hh(0, cur); a0.w16 = wh16_p; a0.bias = g1bh;
        a0.gi = gi1_p; a0.hin = Hf(0, cur); a0.hout = Hf(0, cur ^ 1);
        a0.oh = Hh(0, cur ^ 1); a0.lda = Hdim;
        const int z = (t < T_FUT) ? 2 : 1;
        if (t < T_FUT) {
            a1.a16 = Hh(1, cur); a1.w16 = wh16_p + WN; a1.bias = g2bh;
            a1.gi = gi2_p; a1.hin = Hf(1, cur); a1.hout = Hf(1, cur ^ 1);
            a1.oh = Hh(1, cur ^ 1); a1.lda = Hdim;
        }
        hmma1_kernel<0, 64><<<dim3(16, Bsz / 64, z), 256, DYN_SMEM>>>(a0, a1);

        ProjArgs p0 = {Hf(0, cur ^ 1), fiw, fib, dec, t, T_PAST, 0};
        ProjArgs p1 = {Hf(1, cur ^ 1), fow, fob, fut, t, T_FUT, 1};
        proj4_dual<<<dim3(Bsz / 4, z), 128>>>(p0, p1);
    }
}

// round 9
// speedup vs baseline: 3.7684x; 1.0347x over previous
#include <cuda_runtime.h>
#include <cuda_fp16.h>
#include <cstdint>
#include <math.h>

#define Bsz   8192
#define Hdim  1024
#define H2    512
#define G3    3072
#define T_PAST 60
#define T_FUT  30

// ---------------- scratch (static device globals) ----------------
__device__ float g_ec[Bsz * H2];
__device__ float g_h[2][2][Bsz * Hdim];          // fp32 hidden, [gru][pp]
__device__ __half g_ah[2][2][Bsz * Hdim];        // h as fp16, [gru][pp]
__device__ __half g_gih[2][Bsz * G3];            // gi as fp16
__device__ __half g_wh16[2][G3 * Hdim];          // wh fp16
__device__ __half g_wi16[2][G3 * H2];            // wi fp16
__device__ __half g_ec16[Bsz * H2];              // ec fp16

// ---------------- PTX helpers (sm_80-level, compute_103-safe) ----------------
__device__ __forceinline__ uint32_t smem_u32(const void* p) {
    uint32_t a;
    asm("{ .reg .u64 t; cvta.to.shared.u64 t, %1; cvt.u32.u64 %0, t; }" : "=r"(a) : "l"(p));
    return a;
}
__device__ __forceinline__ void cp16(uint32_t s, const void* g) {
    asm volatile("cp.async.cg.shared.global [%0], [%1], 16;" :: "r"(s), "l"(g));
}
__device__ __forceinline__ void cp_commit() {
    asm volatile("cp.async.commit_group;" ::: "memory");
}
template <int N> __device__ __forceinline__ void cp_wait() {
    asm volatile("cp.async.wait_group %0;" :: "n"(N) : "memory");
}
__device__ __forceinline__ void ldsm_x4(uint32_t* r, uint32_t a) {
    asm volatile("ldmatrix.sync.aligned.m8n8.x4.shared.b16 {%0,%1,%2,%3}, [%4];"
                 : "=r"(r[0]), "=r"(r[1]), "=r"(r[2]), "=r"(r[3]) : "r"(a));
}
__device__ __forceinline__ void mma_f16(float* c, const uint32_t* a, const uint32_t* b) {
    asm volatile(
        "mma.sync.aligned.m16n8k16.row.col.f32.f16.f16.f32 "
        "{%0,%1,%2,%3}, {%4,%5,%6,%7}, {%8,%9}, {%0,%1,%2,%3};"
        : "+f"(c[0]), "+f"(c[1]), "+f"(c[2]), "+f"(c[3])
        : "r"(a[0]), "r"(a[1]), "r"(a[2]), "r"(a[3]), "r"(b[0]), "r"(b[1]));
}

// ---------------- small kernels ----------------
struct F2H4 { const float* s[4]; __half* d[4]; int n[4]; };
__global__ void f2h4_kernel(F2H4 a) {
    const int stride = gridDim.x * blockDim.x;
#pragma unroll
    for (int j = 0; j < 4; j++) {
        for (int i = blockIdx.x * blockDim.x + threadIdx.x; i < a.n[j]; i += stride)
            a.d[j][i] = __float2half(a.s[j][i]);
    }
}

__global__ void f2h_kernel(const float* __restrict__ src, __half* __restrict__ dst, int n) {
    int i = blockIdx.x * blockDim.x + threadIdx.x;
    int stride = gridDim.x * blockDim.x;
    for (; i < n; i += stride) dst[i] = __float2half(src[i]);
}

__global__ void init_h_kernel(const float* __restrict__ ctx) {
    int i = blockIdx.x * blockDim.x + threadIdx.x;
    const int n = Bsz * Hdim;
    const int stride = gridDim.x * blockDim.x;
    for (; i < n; i += stride) {
        float v = ctx[i];
        __half h = __float2half(v);
        g_h[0][0][i] = v;  g_h[1][0][i] = v;
        g_ah[0][0][i] = h; g_ah[1][0][i] = h;
    }
}

// initialize outputs with biases (atomicAdd partials accumulate on top)
__global__ void out_init_kernel(float* __restrict__ dec, float* __restrict__ fut,
                                const float* __restrict__ fib, const float* __restrict__ fob) {
    const int stride = gridDim.x * blockDim.x;
    const int nd = Bsz * T_PAST * 4, nf = Bsz * T_FUT * 4;
    for (int i = blockIdx.x * blockDim.x + threadIdx.x; i < nd; i += stride)
        dec[i] = fib[i & 3];
    for (int i = blockIdx.x * blockDim.x + threadIdx.x; i < nf; i += stride)
        fut[i] = fob[i & 3];
}

// fp32 SIMT GEMM for ec prologue only
__global__ void gemm_bt_kernel(const float* __restrict__ A,
                               const float* __restrict__ W,
                               const float* __restrict__ bias,
                               float* __restrict__ C,
                               int N, int K, int relu) {
    __shared__ float As[16][68];
    __shared__ float Bs[16][68];
    const int t   = threadIdx.x;
    const int tx  = t & 15, ty = t >> 4;
    const int m0  = blockIdx.y << 6, n0 = blockIdx.x << 6;
    const int lrow = t >> 2;
    const int lk   = (t & 3) << 2;

    float acc[4][4] = {};
    const float* Ap = A + (size_t)(m0 + lrow) * K + lk;
    const float* Wp = W + (size_t)(n0 + lrow) * K + lk;

    for (int k0 = 0; k0 < K; k0 += 16) {
        float4 a = *(const float4*)(Ap + k0);
        float4 b = *(const float4*)(Wp + k0);
        __syncthreads();
        As[lk + 0][lrow] = a.x; As[lk + 1][lrow] = a.y;
        As[lk + 2][lrow] = a.z; As[lk + 3][lrow] = a.w;
        Bs[lk + 0][lrow] = b.x; Bs[lk + 1][lrow] = b.y;
        Bs[lk + 2][lrow] = b.z; Bs[lk + 3][lrow] = b.w;
        __syncthreads();
#pragma unroll
        for (int k = 0; k < 16; k++) {
            float4 av = *(const float4*)&As[k][ty << 2];
            float4 bv = *(const float4*)&Bs[k][tx << 2];
            float aa[4] = {av.x, av.y, av.z, av.w};
            float bb[4] = {bv.x, bv.y, bv.z, bv.w};
#pragma unroll
            for (int i = 0; i < 4; i++)
#pragma unroll
                for (int j = 0; j < 4; j++)
                    acc[i][j] += aa[i] * bb[j];
        }
    }
#pragma unroll
    for (int i = 0; i < 4; i++) {
        int m = m0 + (ty << 2) + i;
#pragma unroll
        for (int j = 0; j < 4; j++) {
            int n = n0 + (tx << 2) + j;
            float v = acc[i][j] + bias[n];
            if (relu) v = fmaxf(v, 0.0f);
            C[(size_t)m * N + n] = v;
        }
    }
}

// ---------------- single-term fp16 HMMA 3-gate GEMM + fused GRU + fused proj ----------------
static constexpr int OFF_W    = 64 * 48;                 // 3072
static constexpr int STAGE    = OFF_W + 192 * 48;        // 12288
static constexpr int NS       = 4;
static constexpr int DYN_SMEM = NS * STAGE;              // 49152

struct GemmArgs {
    const __half *a16, *w16;
    const float* bias;         // [3*1024]
    const __half* gi;          // MODE 0
    const float* hin;          // MODE 0
    float*       hout;         // MODE 0
    __half*      oh;           // MODE 0
    __half*      giout;        // MODE 1
    const float* pw;           // MODE 0: proj weight [4,1024]
    float*       pout;         // MODE 0: out + t*4
    int          pstride;      // MODE 0: T*4
    int          prelu;        // MODE 0
    int          lda;          // row stride (elems) of A and W
};

// MODE 0: fused GRU step + proj (K16=64).  MODE 1: gi GEMM + bias -> fp16 (K16=32)
template <int MODE, int K16>
__global__ void __launch_bounds__(256, 2)
hmma1_kernel(GemmArgs arg0, GemmArgs arg1) {
    extern __shared__ char dsmem[];
    __shared__ float s_bh[192];
    __shared__ float s_pw[256];

    const GemmArgs& A = (blockIdx.z == 0) ? arg0 : arg1;

    const int t   = threadIdx.x;
    const int wid = t >> 5, L = t & 31;
    const int n0  = blockIdx.x * 64;     // per-gate column tile
    const int m0  = blockIdx.y * 64;     // batch tile
    const int mwarp = wid >> 2, nwarp = wid & 3;
    const int lda = A.lda;

    const uint32_t dynb = smem_u32(dsmem);

    if (t < 192) s_bh[t] = A.bias[(t >> 6) * 1024 + n0 + (t & 63)];
    if (MODE == 0) s_pw[t] = A.pw[(t >> 6) * 1024 + n0 + (t & 63)];

    // ---- cp.async chunk assignment: 512 x 16B chunks per stage, 2 per thread ----
    const __half* src[2];
    uint32_t dst[2];
#pragma unroll
    for (int j = 0; j < 2; j++) {
        int c = t + 256 * j;
        if (c < 128) {                       // A: 64 rows x 2 halves
            int row = c >> 1, half = c & 1;
            src[j] = A.a16 + (size_t)(m0 + row) * lda + 8 * half;
            dst[j] = (uint32_t)(row * 48 + half * 16);
        } else {                             // W: 192 rows x 2 halves
            int cw = c - 128;
            int row = cw >> 1, half = cw & 1;
            int g = row >> 6, n = row & 63;
            src[j] = A.w16 + (size_t)(g * 1024 + n0 + n) * lda + 8 * half;
            dst[j] = (uint32_t)(OFF_W + row * 48 + half * 16);
        }
    }

    auto load_stage = [&](uint32_t base, int ke) {
        cp16(base + dst[0], src[0] + ke);
        cp16(base + dst[1], src[1] + ke);
    };

    // ---- ldmatrix lane offsets ----
    const uint32_t aoff = (uint32_t)((mwarp * 32 + (L & 15)) * 48 + (L >> 4) * 16);
    uint32_t boff[3];
    {
        int nlane = (L & 7) + ((L & 16) ? 8 : 0);
        int k8 = (L >> 3) & 1;
#pragma unroll
        for (int g = 0; g < 3; g++)
            boff[g] = (uint32_t)(OFF_W + (g * 64 + nwarp * 16 + nlane) * 48 + k8 * 16);
    }

    // ---- pipeline prologue ----
#pragma unroll
    for (int s = 0; s < NS - 1; s++) {
        load_stage(dynb + s * STAGE, s * 16);
        cp_commit();
    }

    float acc[3][2][2][4];   // [gate][m16][n8][4]
#pragma unroll
    for (int g = 0; g < 3; g++)
#pragma unroll
        for (int mt = 0; mt < 2; mt++)
#pragma unroll
            for (int nt = 0; nt < 2; nt++)
#pragma unroll
                for (int e = 0; e < 4; e++) acc[g][mt][nt][e] = 0.0f;

    // ---- main K loop ----
#pragma unroll 1
    for (int ki = 0; ki < K16; ki++) {
        cp_wait<NS - 2>();
        __syncthreads();
        const uint32_t sb = dynb + (uint32_t)(ki & (NS - 1)) * STAGE;

        uint32_t A0[4], A1[4];
        ldsm_x4(A0, sb + aoff);
        ldsm_x4(A1, sb + aoff + 16 * 48);
#pragma unroll
        for (int g = 0; g < 3; g++) {
            uint32_t B[4];
            ldsm_x4(B, sb + boff[g]);
            mma_f16(acc[g][0][0], A0, &B[0]);
            mma_f16(acc[g][0][1], A0, &B[2]);
            mma_f16(acc[g][1][0], A1, &B[0]);
            mma_f16(acc[g][1][1], A1, &B[2]);
        }

        const int kn = ki + NS - 1;
        if (kn < K16) load_stage(dynb + (uint32_t)(kn & (NS - 1)) * STAGE, kn * 16);
        cp_commit();
    }

    // ---- epilogue ----
    const int rq = L >> 2, cq = L & 3;
#pragma unroll
    for (int mt = 0; mt < 2; mt++) {
#pragma unroll
        for (int rs = 0; rs < 2; rs++) {
            const int row = m0 + mwarp * 32 + mt * 16 + rs * 8 + rq;
            if (MODE == 1) {
                __half* go = A.giout + (size_t)row * G3;
#pragma unroll
                for (int g = 0; g < 3; g++)
#pragma unroll
                    for (int nt = 0; nt < 2; nt++) {
                        const int c = nwarp * 16 + nt * 8 + 2 * cq;
                        float v0 = acc[g][mt][nt][rs * 2 + 0] + s_bh[g * 64 + c];
                        float v1 = acc[g][mt][nt][rs * 2 + 1] + s_bh[g * 64 + c + 1];
                        *(__half2*)(go + g * 1024 + n0 + c) = __floats2half2_rn(v0, v1);
                    }
            } else {
                const __half* gib = A.gi + (size_t)row * G3;
                const float* hinr = A.hin + (size_t)row * Hdim;
                float*       hor  = A.hout + (size_t)row * Hdim;
                __half*      hhr  = A.oh  + (size_t)row * Hdim;
                float pacc[4] = {0.f, 0.f, 0.f, 0.f};
#pragma unroll
                for (int nt = 0; nt < 2; nt++) {
                    const int c   = nwarp * 16 + nt * 8 + 2 * cq;
                    const int col = n0 + c;
                    float2 ir  = __half22float2(*(const __half2*)(gib + col));
                    float2 iz  = __half22float2(*(const __half2*)(gib + 1024 + col));
                    float2 inn = __half22float2(*(const __half2*)(gib + 2048 + col));
                    float2 hv  = *(const float2*)(hinr + col);
                    float ira[2] = {ir.x, ir.y};
                    float iza[2] = {iz.x, iz.y};
                    float ina[2] = {inn.x, inn.y};
                    float hva[2] = {hv.x, hv.y};
                    float o[2];
#pragma unroll
                    for (int e = 0; e < 2; e++) {
                        float hr = acc[0][mt][nt][rs * 2 + e] + s_bh[c + e];
                        float hz = acc[1][mt][nt][rs * 2 + e] + s_bh[64 + c + e];
                        float hn = acc[2][mt][nt][rs * 2 + e] + s_bh[128 + c + e];
                        float r = 1.0f / (1.0f + __expf(-(ira[e] + hr)));
                        float z = 1.0f / (1.0f + __expf(-(iza[e] + hz)));
                        float ex = __expf(2.0f * (ina[e] + r * hn));
                        float nn = 1.0f - 2.0f / (ex + 1.0f);
                        o[e] = (1.0f - z) * nn + z * hva[e];
                    }
                    *(float2*)(hor + col) = make_float2(o[0], o[1]);
                    *(__half2*)(hhr + col) = __half2(__float2half(o[0]), __float2half(o[1]));
                    // fused projection partials
                    float p0 = A.prelu ? fmaxf(o[0], 0.0f) : o[0];
                    float p1 = A.prelu ? fmaxf(o[1], 0.0f) : o[1];
#pragma unroll
                    for (int i = 0; i < 4; i++)
                        pacc[i] += p0 * s_pw[i * 64 + c] + p1 * s_pw[i * 64 + c + 1];
                }
                // reduce over cq quad, one atomicAdd per (row, i) per warp
#pragma unroll
                for (int i = 0; i < 4; i++) {
                    float v = pacc[i];
                    v += __shfl_xor_sync(0xffffffffu, v, 1);
                    v += __shfl_xor_sync(0xffffffffu, v, 2);
                    if (cq == 0)
                        atomicAdd(A.pout + (size_t)row * A.pstride + i, v);
                }
            }
        }
    }
}

// ---------------------------------------------------------------------------
extern "C" void kernel_launch(void* const* d_in, const int* in_sizes, int n_in,
                              void* d_out, int out_size) {
    const float* context = (const float*)d_in[0];
    const float* wc      = (const float*)d_in[1];
    const float* bc      = (const float*)d_in[2];
    const float* g1wi    = (const float*)d_in[3];
    const float* g1wh    = (const float*)d_in[4];
    const float* g1bi    = (const float*)d_in[5];
    const float* g1bh    = (const float*)d_in[6];
    const float* g2wi    = (const float*)d_in[7];
    const float* g2wh    = (const float*)d_in[8];
    const float* g2bi    = (const float*)d_in[9];
    const float* g2bh    = (const float*)d_in[10];
    const float* fiw     = (const float*)d_in[11];
    const float* fib     = (const float*)d_in[12];
    const float* fow     = (const float*)d_in[13];
    const float* fob     = (const float*)d_in[14];

    float* dec = (float*)d_out;
    float* fut = (float*)d_out + (size_t)Bsz * T_PAST * 4;

    float *ec_p, *h_p;
    __half *ah_p, *gih_p, *wh16_p, *wi16_p, *ec16_p;
    cudaGetSymbolAddress((void**)&ec_p,   g_ec);
    cudaGetSymbolAddress((void**)&h_p,    g_h);
    cudaGetSymbolAddress((void**)&ah_p,   g_ah);
    cudaGetSymbolAddress((void**)&gih_p,  g_gih);
    cudaGetSymbolAddress((void**)&wh16_p, g_wh16);
    cudaGetSymbolAddress((void**)&wi16_p, g_wi16);
    cudaGetSymbolAddress((void**)&ec16_p, g_ec16);

    const size_t HN  = (size_t)Bsz * Hdim;
    const size_t WN  = (size_t)G3 * Hdim;
    const size_t WIN = (size_t)G3 * H2;
    const size_t GN  = (size_t)Bsz * G3;
    auto Hf = [&](int g, int p) { return h_p  + ((size_t)g * 2 + p) * HN; };
    auto Hh = [&](int g, int p) { return ah_p + ((size_t)g * 2 + p) * HN; };

    cudaFuncSetAttribute(hmma1_kernel<0, 64>, cudaFuncAttributeMaxDynamicSharedMemorySize, DYN_SMEM);
    cudaFuncSetAttribute(hmma1_kernel<1, 32>, cudaFuncAttributeMaxDynamicSharedMemorySize, DYN_SMEM);

    // ---- prologue (ordered so launch #6 is the MODE-1 hmma GEMM for ncu -s 5) ----
    {   // 1: all weight conversions in one kernel
        F2H4 a;
        a.s[0] = g1wh; a.d[0] = wh16_p;       a.n[0] = (int)WN;
        a.s[1] = g2wh; a.d[1] = wh16_p + WN;  a.n[1] = (int)WN;
        a.s[2] = g1wi; a.d[2] = wi16_p;       a.n[2] = (int)WIN;
        a.s[3] = g2wi; a.d[3] = wi16_p + WIN; a.n[3] = (int)WIN;
        f2h4_kernel<<<2048, 256>>>(a);
    }
    // 2: ec = relu(context @ wc^T + bc)
    gemm_bt_kernel<<<dim3(H2 / 64, Bsz / 64), 256>>>(context, wc, bc, ec_p, H2, Hdim, 1);
    // 3: ec -> fp16
    f2h_kernel<<<1024, 256>>>(ec_p, ec16_p, Bsz * H2);
    // 4: h0 = context
    init_h_kernel<<<2048, 256>>>(context);
    // 5: output = bias
    out_init_kernel<<<1024, 256>>>(dec, fut, fib, fob);
    // 6: gi = ec @ wi^T + bi (fp16 out, both GRUs)
    {
        GemmArgs a0 = {}, a1 = {};
        a0.a16 = ec16_p; a0.w16 = wi16_p; a0.bias = g1bi; a0.giout = gih_p; a0.lda = H2;
        a1 = a0;
        a1.w16 = wi16_p + WIN; a1.bias = g2bi; a1.giout = gih_p + GN;
        hmma1_kernel<1, 32><<<dim3(16, Bsz / 64, 2), 256, DYN_SMEM>>>(a0, a1);
    }

    // ---- recurrent steps (proj fused) ----
    for (int t = 0; t < T_PAST; t++) {
        const int cur = t & 1;
        GemmArgs a0 = {}, a1 = {};
        a0.a16 = Hh(0, cur); a0.w16 = wh16_p; a0.bias = g1bh;
        a0.gi = gih_p; a0.hin = Hf(0, cur); a0.hout = Hf(0, cur ^ 1);
        a0.oh = Hh(0, cur ^ 1); a0.lda = Hdim;
        a0.pw = fiw; a0.pout = dec + (size_t)t * 4; a0.pstride = T_PAST * 4; a0.prelu = 0;
        const int z = (t < T_FUT) ? 2 : 1;
        if (t < T_FUT) {
            a1.a16 = Hh(1, cur); a1.w16 = wh16_p + WN; a1.bias = g2bh;
            a1.gi = gih_p + GN; a1.hin = Hf(1, cur); a1.hout = Hf(1, cur ^ 1);
            a1.oh = Hh(1, cur ^ 1); a1.lda = Hdim;
            a1.pw = fow; a1.pout = fut + (size_t)t * 4; a1.pstride = T_FUT * 4; a1.prelu = 1;
        }
        hmma1_kernel<0, 64><<<dim3(16, Bsz / 64, z), 256, DYN_SMEM>>>(a0, a1);
    }
}

// round 13
// speedup vs baseline: 4.4030x; 1.1684x over previous
#include <cuda_runtime.h>
#include <cuda_fp16.h>
#include <cstdint>
#include <math.h>

#define Bsz   8192
#define Hdim  1024
#define H2    512
#define G3    3072
#define T_PAST 60
#define T_FUT  30

// ---------------- scratch (static device globals) ----------------
__device__ float g_ec[Bsz * H2];
__device__ float g_h[2][2][Bsz * Hdim];          // fp32 hidden, [gru][pp]
__device__ __half g_ah[2][2][Bsz * Hdim];        // h as fp16, [gru][pp]
__device__ __half g_gih[2][Bsz * G3];            // gi as fp16
__device__ __half g_wh16[2][G3 * Hdim];          // wh fp16
__device__ __half g_wi16[2][G3 * H2];            // wi fp16
__device__ __half g_ec16[Bsz * H2];              // ec fp16

// ---------------- PTX helpers (sm_80-level, compute_103-safe) ----------------
__device__ __forceinline__ uint32_t smem_u32(const void* p) {
    uint32_t a;
    asm("{ .reg .u64 t; cvta.to.shared.u64 t, %1; cvt.u32.u64 %0, t; }" : "=r"(a) : "l"(p));
    return a;
}
__device__ __forceinline__ void cp16(uint32_t s, const void* g) {
    asm volatile("cp.async.cg.shared.global [%0], [%1], 16;" :: "r"(s), "l"(g));
}
__device__ __forceinline__ void cp_commit() {
    asm volatile("cp.async.commit_group;" ::: "memory");
}
template <int N> __device__ __forceinline__ void cp_wait() {
    asm volatile("cp.async.wait_group %0;" :: "n"(N) : "memory");
}
__device__ __forceinline__ void ldsm_x4(uint32_t* r, uint32_t a) {
    asm volatile("ldmatrix.sync.aligned.m8n8.x4.shared.b16 {%0,%1,%2,%3}, [%4];"
                 : "=r"(r[0]), "=r"(r[1]), "=r"(r[2]), "=r"(r[3]) : "r"(a));
}
__device__ __forceinline__ void mma_f16(float* c, const uint32_t* a, const uint32_t* b) {
    asm volatile(
        "mma.sync.aligned.m16n8k16.row.col.f32.f16.f16.f32 "
        "{%0,%1,%2,%3}, {%4,%5,%6,%7}, {%8,%9}, {%0,%1,%2,%3};"
        : "+f"(c[0]), "+f"(c[1]), "+f"(c[2]), "+f"(c[3])
        : "r"(a[0]), "r"(a[1]), "r"(a[2]), "r"(a[3]), "r"(b[0]), "r"(b[1]));
}

// ---------------- small kernels ----------------
struct F2H4 { const float* s[4]; __half* d[4]; int n[4]; };
__global__ void f2h4_kernel(F2H4 a) {
    const int stride = gridDim.x * blockDim.x;
#pragma unroll
    for (int j = 0; j < 4; j++) {
        for (int i = blockIdx.x * blockDim.x + threadIdx.x; i < a.n[j]; i += stride)
            a.d[j][i] = __float2half(a.s[j][i]);
    }
}

// ec->fp16, h0 init, output bias init — one kernel
__global__ void misc_kernel(const float* __restrict__ ctx,
                            float* __restrict__ dec, float* __restrict__ fut,
                            const float* __restrict__ fib, const float* __restrict__ fob) {
    const int stride = gridDim.x * blockDim.x;
    const int tid0 = blockIdx.x * blockDim.x + threadIdx.x;
    for (int i = tid0; i < Bsz * H2; i += stride)
        g_ec16[i] = __float2half(g_ec[i]);
    for (int i = tid0; i < Bsz * Hdim; i += stride) {
        float v = ctx[i];
        __half h = __float2half(v);
        g_h[0][0][i] = v;  g_h[1][0][i] = v;
        g_ah[0][0][i] = h; g_ah[1][0][i] = h;
    }
    for (int i = tid0; i < Bsz * T_PAST * 4; i += stride) dec[i] = fib[i & 3];
    for (int i = tid0; i < Bsz * T_FUT * 4; i += stride)  fut[i] = fob[i & 3];
}

// fp32 SIMT GEMM for ec prologue only
__global__ void gemm_bt_kernel(const float* __restrict__ A,
                               const float* __restrict__ W,
                               const float* __restrict__ bias,
                               float* __restrict__ C,
                               int N, int K, int relu) {
    __shared__ float As[16][68];
    __shared__ float Bs[16][68];
    const int t   = threadIdx.x;
    const int tx  = t & 15, ty = t >> 4;
    const int m0  = blockIdx.y << 6, n0 = blockIdx.x << 6;
    const int lrow = t >> 2;
    const int lk   = (t & 3) << 2;

    float acc[4][4] = {};
    const float* Ap = A + (size_t)(m0 + lrow) * K + lk;
    const float* Wp = W + (size_t)(n0 + lrow) * K + lk;

    for (int k0 = 0; k0 < K; k0 += 16) {
        float4 a = *(const float4*)(Ap + k0);
        float4 b = *(const float4*)(Wp + k0);
        __syncthreads();
        As[lk + 0][lrow] = a.x; As[lk + 1][lrow] = a.y;
        As[lk + 2][lrow] = a.z; As[lk + 3][lrow] = a.w;
        Bs[lk + 0][lrow] = b.x; Bs[lk + 1][lrow] = b.y;
        Bs[lk + 2][lrow] = b.z; Bs[lk + 3][lrow] = b.w;
        __syncthreads();
#pragma unroll
        for (int k = 0; k < 16; k++) {
            float4 av = *(const float4*)&As[k][ty << 2];
            float4 bv = *(const float4*)&Bs[k][tx << 2];
            float aa[4] = {av.x, av.y, av.z, av.w};
            float bb[4] = {bv.x, bv.y, bv.z, bv.w};
#pragma unroll
            for (int i = 0; i < 4; i++)
#pragma unroll
                for (int j = 0; j < 4; j++)
                    acc[i][j] += aa[i] * bb[j];
        }
    }
#pragma unroll
    for (int i = 0; i < 4; i++) {
        int m = m0 + (ty << 2) + i;
#pragma unroll
        for (int j = 0; j < 4; j++) {
            int n = n0 + (tx << 2) + j;
            float v = acc[i][j] + bias[n];
            if (relu) v = fmaxf(v, 0.0f);
            C[(size_t)m * N + n] = v;
        }
    }
}

// ---------------- fp16 HMMA 3-gate GEMM, M=128 tile, 512 thr ----------------
static constexpr int OFF_W    = 128 * 48;                // 6144
static constexpr int STAGE    = OFF_W + 192 * 48;        // 15360
static constexpr int NS       = 8;
static constexpr int DYN_SMEM = NS * STAGE;              // 122880

struct GemmArgs {
    const __half *a16, *w16;
    const float* bias;         // [3*1024]
    const __half* gi;          // MODE 0
    const float* hin;          // MODE 0
    float*       hout;         // MODE 0
    __half*      oh;           // MODE 0
    __half*      giout;        // MODE 1
    const float* pw;           // MODE 0: proj weight [4,1024]
    float*       pout;         // MODE 0: out + t*4
    int          pstride;      // MODE 0: T*4
    int          prelu;        // MODE 0
    int          lda;          // row stride (elems) of A and W
};

// MODE 0: fused GRU step + proj (K16=64).  MODE 1: gi GEMM + bias -> fp16 (K16=32)
template <int MODE, int K16>
__global__ void __launch_bounds__(512, 1)
hmma1_kernel(GemmArgs arg0, GemmArgs arg1) {
    extern __shared__ char dsmem[];
    __shared__ float s_bh[192];
    __shared__ float s_pw[256];

    const GemmArgs& A = (blockIdx.z == 0) ? arg0 : arg1;

    const int t   = threadIdx.x;
    const int wid = t >> 5, L = t & 31;
    const int n0  = blockIdx.x * 64;     // per-gate column tile
    const int m0  = blockIdx.y * 128;    // batch tile
    const int mwarp = wid >> 2, nwarp = wid & 3;   // 4 x 4
    const int lda = A.lda;

    const uint32_t dynb = smem_u32(dsmem);

    if (t < 192) s_bh[t] = A.bias[(t >> 6) * 1024 + n0 + (t & 63)];
    if (MODE == 0 && t >= 256 && t < 512)
        s_pw[t - 256] = A.pw[((t - 256) >> 6) * 1024 + n0 + ((t - 256) & 63)];

    // ---- cp.async chunk assignment: 640 x 16B chunks per stage ----
    // chunk c < 256: A (128 rows x 2 halves); c >= 256: W (192 rows x 2 halves)
    const __half* src0;
    uint32_t dst0;
    {
        int c = t;
        if (c < 256) {
            int row = c >> 1, half = c & 1;
            src0 = A.a16 + (size_t)(m0 + row) * lda + 8 * half;
            dst0 = (uint32_t)(row * 48 + half * 16);
        } else {
            int cw = c - 256;
            int row = cw >> 1, half = cw & 1;
            int g = row >> 6, n = row & 63;
            src0 = A.w16 + (size_t)(g * 1024 + n0 + n) * lda + 8 * half;
            dst0 = (uint32_t)(OFF_W + row * 48 + half * 16);
        }
    }
    const __half* src1 = nullptr;
    uint32_t dst1 = 0;
    if (t < 128) {
        int cw = (512 + t) - 256;   // 256..383
        int row = cw >> 1, half = cw & 1;
        int g = row >> 6, n = row & 63;
        src1 = A.w16 + (size_t)(g * 1024 + n0 + n) * lda + 8 * half;
        dst1 = (uint32_t)(OFF_W + row * 48 + half * 16);
    }

    auto load_stage = [&](uint32_t base, int ke) {
        cp16(base + dst0, src0 + ke);
        if (t < 128) cp16(base + dst1, src1 + ke);
    };

    // ---- ldmatrix lane offsets ----
    const uint32_t aoff = (uint32_t)((mwarp * 32 + (L & 15)) * 48 + (L >> 4) * 16);
    uint32_t boff[3];
    {
        int nlane = (L & 7) + ((L & 16) ? 8 : 0);
        int k8 = (L >> 3) & 1;
#pragma unroll
        for (int g = 0; g < 3; g++)
            boff[g] = (uint32_t)(OFF_W + (g * 64 + nwarp * 16 + nlane) * 48 + k8 * 16);
    }

    // ---- pipeline prologue ----
#pragma unroll
    for (int s = 0; s < NS - 1; s++) {
        load_stage(dynb + s * STAGE, s * 16);
        cp_commit();
    }

    float acc[3][2][2][4];   // [gate][m16][n8][4]
#pragma unroll
    for (int g = 0; g < 3; g++)
#pragma unroll
        for (int mt = 0; mt < 2; mt++)
#pragma unroll
            for (int nt = 0; nt < 2; nt++)
#pragma unroll
                for (int e = 0; e < 4; e++) acc[g][mt][nt][e] = 0.0f;

    // ---- main K loop ----
#pragma unroll 1
    for (int ki = 0; ki < K16; ki++) {
        cp_wait<NS - 2>();
        __syncthreads();
        const uint32_t sb = dynb + (uint32_t)(ki & (NS - 1)) * STAGE;

        uint32_t A0[4], A1[4];
        ldsm_x4(A0, sb + aoff);
        ldsm_x4(A1, sb + aoff + 16 * 48);
#pragma unroll
        for (int g = 0; g < 3; g++) {
            uint32_t B[4];
            ldsm_x4(B, sb + boff[g]);
            mma_f16(acc[g][0][0], A0, &B[0]);
            mma_f16(acc[g][0][1], A0, &B[2]);
            mma_f16(acc[g][1][0], A1, &B[0]);
            mma_f16(acc[g][1][1], A1, &B[2]);
        }

        const int kn = ki + NS - 1;
        if (kn < K16) load_stage(dynb + (uint32_t)(kn & (NS - 1)) * STAGE, kn * 16);
        cp_commit();
    }

    // ---- epilogue ----
    const int rq = L >> 2, cq = L & 3;
#pragma unroll
    for (int mt = 0; mt < 2; mt++) {
#pragma unroll
        for (int rs = 0; rs < 2; rs++) {
            const int row = m0 + mwarp * 32 + mt * 16 + rs * 8 + rq;
            if (MODE == 1) {
                __half* go = A.giout + (size_t)row * G3;
#pragma unroll
                for (int g = 0; g < 3; g++)
#pragma unroll
                    for (int nt = 0; nt < 2; nt++) {
                        const int c = nwarp * 16 + nt * 8 + 2 * cq;
                        float v0 = acc[g][mt][nt][rs * 2 + 0] + s_bh[g * 64 + c];
                        float v1 = acc[g][mt][nt][rs * 2 + 1] + s_bh[g * 64 + c + 1];
                        *(__half2*)(go + g * 1024 + n0 + c) = __floats2half2_rn(v0, v1);
                    }
            } else {
                const __half* gib = A.gi + (size_t)row * G3;
                const float* hinr = A.hin + (size_t)row * Hdim;
                float*       hor  = A.hout + (size_t)row * Hdim;
                __half*      hhr  = A.oh  + (size_t)row * Hdim;
                float pacc[4] = {0.f, 0.f, 0.f, 0.f};
#pragma unroll
                for (int nt = 0; nt < 2; nt++) {
                    const int c   = nwarp * 16 + nt * 8 + 2 * cq;
                    const int col = n0 + c;
                    float2 ir  = __half22float2(*(const __half2*)(gib + col));
                    float2 iz  = __half22float2(*(const __half2*)(gib + 1024 + col));
                    float2 inn = __half22float2(*(const __half2*)(gib + 2048 + col));
                    float2 hv  = *(const float2*)(hinr + col);
                    float ira[2] = {ir.x, ir.y};
                    float iza[2] = {iz.x, iz.y};
                    float ina[2] = {inn.x, inn.y};
                    float hva[2] = {hv.x, hv.y};
                    float o[2];
#pragma unroll
                    for (int e = 0; e < 2; e++) {
                        float hr = acc[0][mt][nt][rs * 2 + e] + s_bh[c + e];
                        float hz = acc[1][mt][nt][rs * 2 + e] + s_bh[64 + c + e];
                        float hn = acc[2][mt][nt][rs * 2 + e] + s_bh[128 + c + e];
                        float r = 1.0f / (1.0f + __expf(-(ira[e] + hr)));
                        float z = 1.0f / (1.0f + __expf(-(iza[e] + hz)));
                        float ex = __expf(2.0f * (ina[e] + r * hn));
                        float nn = 1.0f - 2.0f / (ex + 1.0f);
                        o[e] = (1.0f - z) * nn + z * hva[e];
                    }
                    *(float2*)(hor + col) = make_float2(o[0], o[1]);
                    *(__half2*)(hhr + col) = __half2(__float2half(o[0]), __float2half(o[1]));
                    float p0 = A.prelu ? fmaxf(o[0], 0.0f) : o[0];
                    float p1 = A.prelu ? fmaxf(o[1], 0.0f) : o[1];
#pragma unroll
                    for (int i = 0; i < 4; i++)
                        pacc[i] += p0 * s_pw[i * 64 + c] + p1 * s_pw[i * 64 + c + 1];
                }
#pragma unroll
                for (int i = 0; i < 4; i++) {
                    float v = pacc[i];
                    v += __shfl_xor_sync(0xffffffffu, v, 1);
                    v += __shfl_xor_sync(0xffffffffu, v, 2);
                    if (cq == 0)
                        atomicAdd(A.pout + (size_t)row * A.pstride + i, v);
                }
            }
        }
    }
}

// ---------------------------------------------------------------------------
extern "C" void kernel_launch(void* const* d_in, const int* in_sizes, int n_in,
                              void* d_out, int out_size) {
    const float* context = (const float*)d_in[0];
    const float* wc      = (const float*)d_in[1];
    const float* bc      = (const float*)d_in[2];
    const float* g1wi    = (const float*)d_in[3];
    const float* g1wh    = (const float*)d_in[4];
    const float* g1bi    = (const float*)d_in[5];
    const float* g1bh    = (const float*)d_in[6];
    const float* g2wi    = (const float*)d_in[7];
    const float* g2wh    = (const float*)d_in[8];
    const float* g2bi    = (const float*)d_in[9];
    const float* g2bh    = (const float*)d_in[10];
    const float* fiw     = (const float*)d_in[11];
    const float* fib     = (const float*)d_in[12];
    const float* fow     = (const float*)d_in[13];
    const float* fob     = (const float*)d_in[14];

    float* dec = (float*)d_out;
    float* fut = (float*)d_out + (size_t)Bsz * T_PAST * 4;

    float *ec_p, *h_p;
    __half *ah_p, *gih_p, *wh16_p, *wi16_p, *ec16_p;
    cudaGetSymbolAddress((void**)&ec_p,   g_ec);
    cudaGetSymbolAddress((void**)&h_p,    g_h);
    cudaGetSymbolAddress((void**)&ah_p,   g_ah);
    cudaGetSymbolAddress((void**)&gih_p,  g_gih);
    cudaGetSymbolAddress((void**)&wh16_p, g_wh16);
    cudaGetSymbolAddress((void**)&wi16_p, g_wi16);
    cudaGetSymbolAddress((void**)&ec16_p, g_ec16);

    const size_t HN  = (size_t)Bsz * Hdim;
    const size_t WN  = (size_t)G3 * Hdim;
    const size_t WIN = (size_t)G3 * H2;
    const size_t GN  = (size_t)Bsz * G3;
    auto Hf = [&](int g, int p) { return h_p  + ((size_t)g * 2 + p) * HN; };
    auto Hh = [&](int g, int p) { return ah_p + ((size_t)g * 2 + p) * HN; };

    cudaFuncSetAttribute(hmma1_kernel<0, 64>, cudaFuncAttributeMaxDynamicSharedMemorySize, DYN_SMEM);
    cudaFuncSetAttribute(hmma1_kernel<1, 32>, cudaFuncAttributeMaxDynamicSharedMemorySize, DYN_SMEM);

    // ---- prologue (4 launches; our #4 = hmma GEMM for ncu capture) ----
    {   // 1: all weight conversions
        F2H4 a;
        a.s[0] = g1wh; a.d[0] = wh16_p;       a.n[0] = (int)WN;
        a.s[1] = g2wh; a.d[1] = wh16_p + WN;  a.n[1] = (int)WN;
        a.s[2] = g1wi; a.d[2] = wi16_p;       a.n[2] = (int)WIN;
        a.s[3] = g2wi; a.d[3] = wi16_p + WIN; a.n[3] = (int)WIN;
        f2h4_kernel<<<2048, 256>>>(a);
    }
    // 2: ec = relu(context @ wc^T + bc)
    gemm_bt_kernel<<<dim3(H2 / 64, Bsz / 64), 256>>>(context, wc, bc, ec_p, H2, Hdim, 1);
    // 3: ec->fp16, h0 init, out bias init
    misc_kernel<<<2048, 256>>>(context, dec, fut, fib, fob);
    // 4: gi = ec @ wi^T + bi (fp16 out, both GRUs)
    {
        GemmArgs a0 = {}, a1 = {};
        a0.a16 = ec16_p; a0.w16 = wi16_p; a0.bias = g1bi; a0.giout = gih_p; a0.lda = H2;
        a1 = a0;
        a1.w16 = wi16_p + WIN; a1.bias = g2bi; a1.giout = gih_p + GN;
        hmma1_kernel<1, 32><<<dim3(16, Bsz / 128, 2), 512, DYN_SMEM>>>(a0, a1);
    }

    // ---- recurrent steps (proj fused) ----
    for (int t = 0; t < T_PAST; t++) {
        const int cur = t & 1;
        GemmArgs a0 = {}, a1 = {};
        a0.a16 = Hh(0, cur); a0.w16 = wh16_p; a0.bias = g1bh;
        a0.gi = gih_p; a0.hin = Hf(0, cur); a0.hout = Hf(0, cur ^ 1);
        a0.oh = Hh(0, cur ^ 1); a0.lda = Hdim;
        a0.pw = fiw; a0.pout = dec + (size_t)t * 4; a0.pstride = T_PAST * 4; a0.prelu = 0;
        const int z = (t < T_FUT) ? 2 : 1;
        if (t < T_FUT) {
            a1.a16 = Hh(1, cur); a1.w16 = wh16_p + WN; a1.bias = g2bh;
            a1.gi = gih_p + GN; a1.hin = Hf(1, cur); a1.hout = Hf(1, cur ^ 1);
            a1.oh = Hh(1, cur ^ 1); a1.lda = Hdim;
            a1.pw = fow; a1.pout = fut + (size_t)t * 4; a1.pstride = T_FUT * 4; a1.prelu = 1;
        }
        hmma1_kernel<0, 64><<<dim3(16, Bsz / 128, z), 512, DYN_SMEM>>>(a0, a1);
    }
}